// round 5
// baseline (speedup 1.0000x reference)
#include <cuda_runtime.h>
#include <cuda_bf16.h>
#include <cstdint>

#define NN 50000
#define NE 800000
#define FIN 128
#define HC 128      // HEADS*HID = 4*32
#define NH 4
#define CH 32
#define NOUT 32

// ------------------------- device scratch (no allocation allowed) -------------------------
__device__ float g_hproj[(size_t)NN * HC];
__device__ float g_hskip[(size_t)NN * HC];
__device__ float g_feat1[(size_t)NN * HC];
__device__ float g_feat2[(size_t)NN * HC];
__device__ float g_hskip32[(size_t)NN * NOUT];
__device__ float g_als[(size_t)NN * NH];
__device__ float g_ald[(size_t)NN * NH];
__device__ int   g_deg[NN];
__device__ int   g_cursor[NN];
__device__ int   g_rowptr[NN + 1];
__device__ int   g_csr[NE];

#define SEL_EXT     0
#define SEL_HPROJ   1
#define SEL_HSKIP   2
#define SEL_FEAT1   3
#define SEL_FEAT2   4
#define SEL_HSKIP32 5

__device__ __forceinline__ float* selbuf(int sel, float* ext) {
    switch (sel) {
        case SEL_HPROJ:   return g_hproj;
        case SEL_HSKIP:   return g_hskip;
        case SEL_FEAT1:   return g_feat1;
        case SEL_FEAT2:   return g_feat2;
        case SEL_HSKIP32: return g_hskip32;
        default:          return ext;
    }
}
__device__ __forceinline__ const float* selbuf_c(int sel, const float* ext) {
    return selbuf(sel, (float*)ext);
}

// ------------------------- f32x2 packed math helpers -------------------------
__device__ __forceinline__ unsigned long long pk2(float x, float y) {
    unsigned long long r;
    asm("mov.b64 %0,{%1,%2};" : "=l"(r) : "f"(x), "f"(y));
    return r;
}
__device__ __forceinline__ void upk2(unsigned long long v, float& x, float& y) {
    asm("mov.b64 {%0,%1},%2;" : "=f"(x), "=f"(y) : "l"(v));
}
__device__ __forceinline__ unsigned long long ffma2(unsigned long long a, unsigned long long b,
                                                    unsigned long long c) {
    unsigned long long d;
    asm("fma.rn.f32x2 %0,%1,%2,%3;" : "=l"(d) : "l"(a), "l"(b), "l"(c));
    return d;
}

// ------------------------- CSR build -------------------------
__global__ void zero_kernel() {
    int i = blockIdx.x * blockDim.x + threadIdx.x;
    if (i < NN) { g_deg[i] = 0; g_cursor[i] = 0; }
}

__global__ void count_kernel(const int* __restrict__ dst) {
    int i = blockIdx.x * blockDim.x + threadIdx.x;
    if (i < NE) atomicAdd(&g_deg[dst[i]], 1);
}

// exclusive scan of g_deg into g_rowptr, g_rowptr[NN]=total. Single block.
__global__ void scan_kernel() {
    __shared__ int sh[1024];
    __shared__ int carry;
    if (threadIdx.x == 0) carry = 0;
    __syncthreads();
    for (int base = 0; base < NN; base += 1024) {
        int i = base + threadIdx.x;
        int v = (i < NN) ? g_deg[i] : 0;
        sh[threadIdx.x] = v;
        __syncthreads();
        for (int off = 1; off < 1024; off <<= 1) {
            int t = 0;
            if ((int)threadIdx.x >= off) t = sh[threadIdx.x - off];
            __syncthreads();
            sh[threadIdx.x] += t;
            __syncthreads();
        }
        if (i < NN) g_rowptr[i] = carry + sh[threadIdx.x] - v;
        __syncthreads();
        if (threadIdx.x == 0) carry += sh[1023];
        __syncthreads();
    }
    if (threadIdx.x == 0) g_rowptr[NN] = carry;
}

__global__ void scatter_kernel(const int* __restrict__ src, const int* __restrict__ dst) {
    int i = blockIdx.x * blockDim.x + threadIdx.x;
    if (i < NE) {
        int d = dst[i];
        int pos = g_rowptr[d] + atomicAdd(&g_cursor[d], 1);
        g_csr[pos] = src[i];
    }
}

// ------------------------- dual SGEMM (f32x2, double-buffered) -------------------------
// blockIdx.x selects (B1,bias1,C1) or (B2,bias2,C2); both share A.
// C[M,N] = A[M,K] @ B[K,N] (+ bias). K multiple of BK, N multiple of BN (per selected GEMM).
template <int BM, int BN, int BK, int TM, int TN>
__global__ void __launch_bounds__((BM / TM) * (BN / TN), 2)
sgemm_dual_kernel(const float* __restrict__ Aext, int Asel,
                  const float* __restrict__ B1, const float* __restrict__ bias1, int Csel1,
                  const float* __restrict__ B2, const float* __restrict__ bias2, int Csel2,
                  float* __restrict__ Cext,
                  int M, int N, int K) {
    const float* A = selbuf_c(Asel, Aext);
    const float* B = (blockIdx.x == 0) ? B1 : B2;
    const float* bias = (blockIdx.x == 0) ? bias1 : bias2;
    float* C = selbuf((blockIdx.x == 0) ? Csel1 : Csel2, Cext);

    constexpr int NT = (BM / TM) * (BN / TN);
    constexpr int AR = (BM * BK) / (4 * NT);   // float4 A loads per thread
    constexpr int BR = (BK * BN) / (4 * NT);   // float4 B loads per thread
    static_assert(AR >= 1 && BR >= 1, "tile too small");

    __shared__ float As[2][BK][BM + 4];
    __shared__ float Bs[2][BK][BN];

    int tid = threadIdx.x;
    int m0 = blockIdx.y * BM;
    int n0 = 0;  // BN == N for all uses here
    int tx = tid % (BN / TN);
    int ty = tid / (BN / TN);

    unsigned long long acc[TM][TN / 2];
#pragma unroll
    for (int i = 0; i < TM; i++)
#pragma unroll
        for (int j = 0; j < TN / 2; j++) acc[i][j] = 0ull;

    float4 pa[AR], pb[BR];

    auto fetch = [&](int k0) {
#pragma unroll
        for (int it = 0; it < AR; it++) {
            int idx = tid + it * NT;
            int r = idx / (BK / 4);
            int c = (idx % (BK / 4)) * 4;
            pa[it] = (m0 + r < M) ? *(const float4*)&A[(size_t)(m0 + r) * K + k0 + c]
                                  : make_float4(0.f, 0.f, 0.f, 0.f);
        }
#pragma unroll
        for (int it = 0; it < BR; it++) {
            int idx = tid + it * NT;
            int r = idx / (BN / 4);
            int c = (idx % (BN / 4)) * 4;
            pb[it] = *(const float4*)&B[(size_t)(k0 + r) * N + n0 + c];
        }
    };
    auto stage = [&](int buf) {
#pragma unroll
        for (int it = 0; it < AR; it++) {
            int idx = tid + it * NT;
            int r = idx / (BK / 4);
            int c = (idx % (BK / 4)) * 4;
            As[buf][c + 0][r] = pa[it].x;
            As[buf][c + 1][r] = pa[it].y;
            As[buf][c + 2][r] = pa[it].z;
            As[buf][c + 3][r] = pa[it].w;
        }
#pragma unroll
        for (int it = 0; it < BR; it++) {
            int idx = tid + it * NT;
            int r = idx / (BN / 4);
            int c = (idx % (BN / 4)) * 4;
            *(float4*)&Bs[buf][r][c] = pb[it];
        }
    };

    fetch(0);
    stage(0);
    __syncthreads();

    int nb = K / BK;
    for (int t = 0; t < nb; t++) {
        if (t + 1 < nb) fetch((t + 1) * BK);
        int cur = t & 1;
#pragma unroll
        for (int k = 0; k < BK; k++) {
            unsigned long long a2[TM];
#pragma unroll
            for (int i = 0; i < TM; i += 4) {
                float4 av = *(const float4*)&As[cur][k][ty * TM + i];
                a2[i + 0] = pk2(av.x, av.x);
                a2[i + 1] = pk2(av.y, av.y);
                a2[i + 2] = pk2(av.z, av.z);
                a2[i + 3] = pk2(av.w, av.w);
            }
            unsigned long long b2[TN / 2];
#pragma unroll
            for (int j = 0; j < TN; j += 4) {
                ulonglong2 bv = *(const ulonglong2*)&Bs[cur][k][tx * TN + j];
                b2[j / 2 + 0] = bv.x;
                b2[j / 2 + 1] = bv.y;
            }
#pragma unroll
            for (int i = 0; i < TM; i++)
#pragma unroll
                for (int j = 0; j < TN / 2; j++) acc[i][j] = ffma2(a2[i], b2[j], acc[i][j]);
        }
        if (t + 1 < nb) {
            stage((t + 1) & 1);
            __syncthreads();
        }
    }

#pragma unroll
    for (int i = 0; i < TM; i++) {
        int row = m0 + ty * TM + i;
        if (row < M) {
#pragma unroll
            for (int j = 0; j < TN / 2; j++) {
                int col = n0 + tx * TN + 2 * j;
                float c0, c1;
                upk2(acc[i][j], c0, c1);
                if (bias) {
                    c0 += __ldg(&bias[col]);
                    c1 += __ldg(&bias[col + 1]);
                }
                *(float2*)&C[(size_t)row * N + col] = make_float2(c0, c1);
            }
        }
    }
}

// ------------------------- attention logits -------------------------
__global__ void al_kernel(const float* __restrict__ aS, const float* __restrict__ aD) {
    int idx = blockIdx.x * blockDim.x + threadIdx.x;
    if (idx >= NN * NH) return;
    int n = idx >> 2;
    int h = idx & 3;
    const float* hp = &g_hproj[(size_t)n * HC + h * CH];
    const float* as = &aS[h * CH];
    const float* ad = &aD[h * CH];
    float s1 = 0.f, s2 = 0.f;
#pragma unroll
    for (int c = 0; c < CH; c += 4) {
        float4 hv = *(const float4*)&hp[c];
        float4 av = __ldg((const float4*)&as[c]);
        float4 dv = __ldg((const float4*)&ad[c]);
        s1 += hv.x * av.x + hv.y * av.y + hv.z * av.z + hv.w * av.w;
        s2 += hv.x * dv.x + hv.y * dv.y + hv.z * dv.z + hv.w * dv.w;
    }
    g_als[idx] = s1;
    g_ald[idx] = s2;
}

__device__ __forceinline__ float lrelu(float x) { return x > 0.f ? x : 0.2f * x; }

// ------------------------- aggregation (softmax + weighted sum) -------------------------
// warp-per-(node,head): block = 256 threads = 8 warps = 2 nodes x 4 heads.
// NN is even and grid = NN/2, so every warp has a valid node (no early return).
// mode 0: concat+bias+skip+ELU -> out[N,128]
// mode 1: head-mean + bias + skip + L2-normalize -> out[N,32]
__global__ void __launch_bounds__(256) agg_kernel(int skipsel, const float* __restrict__ bias,
                                                  float* __restrict__ outext, int outsel, int mode) {
    const float* hskip = selbuf_c(skipsel, nullptr);
    float* outp = selbuf(outsel, outext);
    __shared__ float sacc[2][4][32];

    int w = threadIdx.x >> 5;
    int lane = threadIdx.x & 31;
    int ln = w >> 2;        // local node 0..1
    int h = w & 3;          // head
    int n = blockIdx.x * 2 + ln;
    int beg = g_rowptr[n], end = g_rowptr[n + 1];
    float adh = g_ald[(size_t)n * 4 + h];

    // pass 1: max
    float mx = -1e30f;
    for (int j = beg + lane; j < end; j += 32) {
        int s = __ldg(&g_csr[j]);
        mx = fmaxf(mx, lrelu(__ldg(&g_als[(size_t)s * 4 + h]) + adh));
    }
#pragma unroll
    for (int o = 16; o > 0; o >>= 1) mx = fmaxf(mx, __shfl_xor_sync(0xffffffffu, mx, o));

    // pass 2: sum of exp
    float sum = 0.f;
    for (int j = beg + lane; j < end; j += 32) {
        int s = __ldg(&g_csr[j]);
        sum += __expf(lrelu(__ldg(&g_als[(size_t)s * 4 + h]) + adh) - mx);
    }
#pragma unroll
    for (int o = 16; o > 0; o >>= 1) sum += __shfl_xor_sync(0xffffffffu, sum, o);
    float inv = 1.f / (sum + 1e-16f);

    // pass 3: weighted gather; alphas broadcast via shfl
    float acc = 0.f;
    for (int base = beg; base < end; base += 32) {
        int j = base + lane;
        int sr = 0;
        float al = 0.f;
        if (j < end) {
            sr = __ldg(&g_csr[j]);
            al = __expf(lrelu(__ldg(&g_als[(size_t)sr * 4 + h]) + adh) - mx) * inv;
        }
        int cnt = min(32, end - base);
#pragma unroll 4
        for (int k = 0; k < cnt; k++) {
            int s2 = __shfl_sync(0xffffffffu, sr, k);
            float a2 = __shfl_sync(0xffffffffu, al, k);
            acc += a2 * __ldg(&g_hproj[(size_t)s2 * HC + h * 32 + lane]);
        }
    }

    if (mode == 0) {
        int c = h * 32 + lane;
        float v = acc + __ldg(&bias[c]) + hskip[(size_t)n * HC + c];
        v = v > 0.f ? v : expm1f(v);
        outp[(size_t)n * HC + c] = v;
    } else {
        sacc[ln][h][lane] = acc;
        __syncthreads();
        if (h == 0) {
            float v = 0.25f * (sacc[ln][0][lane] + sacc[ln][1][lane] +
                               sacc[ln][2][lane] + sacc[ln][3][lane]) +
                      __ldg(&bias[lane]) + hskip[(size_t)n * NOUT + lane];
            float ss = v * v;
#pragma unroll
            for (int o = 16; o > 0; o >>= 1) ss += __shfl_xor_sync(0xffffffffu, ss, o);
            float r = sqrtf(ss);
            outp[(size_t)n * NOUT + lane] = v / fmaxf(r, 1e-12f);
        }
    }
}

// ------------------------- launch -------------------------
extern "C" void kernel_launch(void* const* d_in, const int* in_sizes, int n_in,
                              void* d_out, int out_size) {
    const float* x = (const float*)d_in[0];
    const int* ei = (const int*)d_in[1];
    const int* src = ei;
    const int* dst = ei + NE;
    const float* W0 = (const float*)d_in[2];
    const float* aS0 = (const float*)d_in[3];
    const float* aD0 = (const float*)d_in[4];
    const float* b0 = (const float*)d_in[5];
    const float* Ws0 = (const float*)d_in[6];
    const float* bs0 = (const float*)d_in[7];
    const float* W1 = (const float*)d_in[8];
    const float* aS1 = (const float*)d_in[9];
    const float* aD1 = (const float*)d_in[10];
    const float* b1 = (const float*)d_in[11];
    const float* Ws1 = (const float*)d_in[12];
    const float* bs1 = (const float*)d_in[13];
    const float* W2 = (const float*)d_in[14];
    const float* aS2 = (const float*)d_in[15];
    const float* aD2 = (const float*)d_in[16];
    const float* b2 = (const float*)d_in[17];
    const float* Ws2 = (const float*)d_in[18];
    const float* bs2 = (const float*)d_in[19];
    float* out = (float*)d_out;

    // ---- CSR build ----
    zero_kernel<<<(NN + 255) / 256, 256>>>();
    count_kernel<<<(NE + 255) / 256, 256>>>(dst);
    scan_kernel<<<1, 1024>>>();
    scatter_kernel<<<(NE + 255) / 256, 256>>>(src, dst);

    dim3 gdual(2, (NN + 127) / 128);
    dim3 gsingle(1, (NN + 127) / 128);
    int aggBlocks = NN / 2;

    // ---- layer 0 ----
    sgemm_dual_kernel<128, 128, 16, 8, 8><<<gdual, 256>>>(
        x, SEL_EXT, W0, nullptr, SEL_HPROJ, Ws0, bs0, SEL_HSKIP, nullptr, NN, HC, FIN);
    al_kernel<<<(NN * NH + 255) / 256, 256>>>(aS0, aD0);
    agg_kernel<<<aggBlocks, 256>>>(SEL_HSKIP, b0, nullptr, SEL_FEAT1, 0);

    // ---- layer 1 ----
    sgemm_dual_kernel<128, 128, 16, 8, 8><<<gdual, 256>>>(
        nullptr, SEL_FEAT1, W1, nullptr, SEL_HPROJ, Ws1, bs1, SEL_HSKIP, nullptr, NN, HC, HC);
    al_kernel<<<(NN * NH + 255) / 256, 256>>>(aS1, aD1);
    agg_kernel<<<aggBlocks, 256>>>(SEL_HSKIP, b1, nullptr, SEL_FEAT2, 0);

    // ---- layer 2 ----
    sgemm_dual_kernel<128, 128, 16, 8, 8><<<gsingle, 256>>>(
        nullptr, SEL_FEAT2, W2, nullptr, SEL_HPROJ, W2, nullptr, SEL_HPROJ, nullptr, NN, HC, HC);
    sgemm_dual_kernel<128, 32, 16, 8, 4><<<dim3(1, (NN + 127) / 128), 128>>>(
        nullptr, SEL_FEAT2, Ws2, bs2, SEL_HSKIP32, Ws2, bs2, SEL_HSKIP32, nullptr, NN, NOUT, HC);
    al_kernel<<<(NN * NH + 255) / 256, 256>>>(aS2, aD2);
    agg_kernel<<<aggBlocks, 256>>>(SEL_HSKIP32, b2, out, SEL_EXT, 1);
}

// round 7
// speedup vs baseline: 1.2323x; 1.2323x over previous
#include <cuda_runtime.h>
#include <cuda_bf16.h>
#include <cstdint>

#define NN 50000
#define NE 800000
#define FIN 128
#define HC 128      // HEADS*HID = 4*32
#define NH 4
#define CH 32
#define NOUT 32

// ------------------------- device scratch (no allocation allowed) -------------------------
__device__ float g_hproj[(size_t)NN * HC];
__device__ float g_hskip[(size_t)NN * HC];
__device__ float g_feat1[(size_t)NN * HC];
__device__ float g_feat2[(size_t)NN * HC];
__device__ float g_hskip32[(size_t)NN * NOUT];
__device__ float g_als[(size_t)NN * NH];
__device__ float g_ald[(size_t)NN * NH];
__device__ int   g_deg[NN];
__device__ int   g_cursor[NN];
__device__ int   g_rowptr[NN + 1];
__device__ int   g_csr[NE];

#define SEL_EXT     0
#define SEL_HPROJ   1
#define SEL_HSKIP   2
#define SEL_FEAT1   3
#define SEL_FEAT2   4
#define SEL_HSKIP32 5

__device__ __forceinline__ float* selbuf(int sel, float* ext) {
    switch (sel) {
        case SEL_HPROJ:   return g_hproj;
        case SEL_HSKIP:   return g_hskip;
        case SEL_FEAT1:   return g_feat1;
        case SEL_FEAT2:   return g_feat2;
        case SEL_HSKIP32: return g_hskip32;
        default:          return ext;
    }
}
__device__ __forceinline__ const float* selbuf_c(int sel, const float* ext) {
    return selbuf(sel, (float*)ext);
}

// ------------------------- CSR build -------------------------
__global__ void zero_kernel() {
    int i = blockIdx.x * blockDim.x + threadIdx.x;
    if (i < NN) { g_deg[i] = 0; g_cursor[i] = 0; }
}
__global__ void count_kernel(const int* __restrict__ dst) {
    int i = blockIdx.x * blockDim.x + threadIdx.x;
    if (i < NE) atomicAdd(&g_deg[dst[i]], 1);
}
__global__ void scan_kernel() {
    __shared__ int sh[1024];
    __shared__ int carry;
    if (threadIdx.x == 0) carry = 0;
    __syncthreads();
    for (int base = 0; base < NN; base += 1024) {
        int i = base + threadIdx.x;
        int v = (i < NN) ? g_deg[i] : 0;
        sh[threadIdx.x] = v;
        __syncthreads();
        for (int off = 1; off < 1024; off <<= 1) {
            int t = 0;
            if ((int)threadIdx.x >= off) t = sh[threadIdx.x - off];
            __syncthreads();
            sh[threadIdx.x] += t;
            __syncthreads();
        }
        if (i < NN) g_rowptr[i] = carry + sh[threadIdx.x] - v;
        __syncthreads();
        if (threadIdx.x == 0) carry += sh[1023];
        __syncthreads();
    }
    if (threadIdx.x == 0) g_rowptr[NN] = carry;
}
__global__ void scatter_kernel(const int* __restrict__ src, const int* __restrict__ dst) {
    int i = blockIdx.x * blockDim.x + threadIdx.x;
    if (i < NE) {
        int d = dst[i];
        int pos = g_rowptr[d] + atomicAdd(&g_cursor[d], 1);
        g_csr[pos] = src[i];
    }
}

// ------------------------- bf16 split HMMA GEMM -------------------------
// C[M,N] = A[M,128] @ B[128,N] (+bias), fp32 in/out.
// A,B staged to smem as bf16 hi/lo; 3 passes (hi*hi + lo*hi + hi*lo) in fp32 accum.
// mma.sync m16n8k16 (baseline PTX -> works on sm_103 without 'a' features).
__device__ __forceinline__ void mma16816(float* c, const uint32_t* a, const uint32_t* b) {
    asm volatile(
        "mma.sync.aligned.m16n8k16.row.col.f32.bf16.bf16.f32 "
        "{%0,%1,%2,%3}, {%4,%5,%6,%7}, {%8,%9}, {%0,%1,%2,%3};"
        : "+f"(c[0]), "+f"(c[1]), "+f"(c[2]), "+f"(c[3])
        : "r"(a[0]), "r"(a[1]), "r"(a[2]), "r"(a[3]), "r"(b[0]), "r"(b[1]));
}
__device__ __forceinline__ uint32_t ld32bf(const __nv_bfloat16* p) {
    return *(const uint32_t*)p;
}

// BN in {128,32}; WM warp tile M (64 for BN=128 -> 2x4 warps; 16 for BN=32 -> 8x1 warps)
template <int BN, int WM>
__global__ void __launch_bounds__(256) bgemm_kernel(
    const float* __restrict__ Aext, int Asel,
    const float* __restrict__ B, const float* __restrict__ bias,
    float* __restrict__ Cext, int Csel, int M, int N) {
    const float* A = selbuf_c(Asel, Aext);
    float* C = selbuf(Csel, Cext);

    constexpr int SA = 136;               // bf16 stride (conflict-free fragment LDS)
    constexpr int MT = WM / 16;
    constexpr int WARPS_N = BN / 32;
    extern __shared__ __nv_bfloat16 sm[];
    __nv_bfloat16* sAhi = sm;
    __nv_bfloat16* sAlo = sm + 128 * SA;
    __nv_bfloat16* sBhi = sm + 2 * 128 * SA;
    __nv_bfloat16* sBlo = sBhi + BN * SA;

    int tid = threadIdx.x;
    int lane = tid & 31, w = tid >> 5;
    int m0 = blockIdx.y * 128;
    int n0 = blockIdx.x * BN;

    // ---- stage A[m0:m0+128, 0:128] fp32 -> bf16 hi/lo ----
#pragma unroll
    for (int j = 0; j < 16; j++) {
        int idx = tid + j * 256;          // 128*128/4 = 4096 float4
        int r = idx >> 5;
        int c = (idx & 31) * 4;
        float4 v = make_float4(0.f, 0.f, 0.f, 0.f);
        if (m0 + r < M) v = *(const float4*)&A[(size_t)(m0 + r) * 128 + c];
        float vv[4] = {v.x, v.y, v.z, v.w};
#pragma unroll
        for (int e = 0; e < 4; e++) {
            __nv_bfloat16 hi = __float2bfloat16(vv[e]);
            sAhi[r * SA + c + e] = hi;
            sAlo[r * SA + c + e] = __float2bfloat16(vv[e] - __bfloat162float(hi));
        }
    }
    // ---- stage B[0:128, n0:n0+BN] fp32 -> bf16 hi/lo, transposed to [n][k] ----
#pragma unroll
    for (int j = 0; j < (128 * BN) / (4 * 256); j++) {
        int idx = tid + j * 256;
        int k = idx / (BN / 4);
        int c = (idx % (BN / 4)) * 4;
        float4 v = *(const float4*)&B[(size_t)k * N + n0 + c];
        float vv[4] = {v.x, v.y, v.z, v.w};
#pragma unroll
        for (int e = 0; e < 4; e++) {
            __nv_bfloat16 hi = __float2bfloat16(vv[e]);
            sBhi[(c + e) * SA + k] = hi;
            sBlo[(c + e) * SA + k] = __float2bfloat16(vv[e] - __bfloat162float(hi));
        }
    }
    __syncthreads();

    int wm = w / WARPS_N, wn = w % WARPS_N;
    int mo = wm * WM, no = wn * 32;
    int g = lane >> 2, t = lane & 3;

    float acc[MT][4][4] = {};

#pragma unroll
    for (int k0 = 0; k0 < 128; k0 += 16) {
        uint32_t ah[MT][4], al_[MT][4], bh[4][2], bl[4][2];
#pragma unroll
        for (int mt = 0; mt < MT; mt++) {
            const __nv_bfloat16* p = sAhi + (mo + mt * 16 + g) * SA + k0 + 2 * t;
            ah[mt][0] = ld32bf(p);
            ah[mt][1] = ld32bf(p + 8 * SA);
            ah[mt][2] = ld32bf(p + 8);
            ah[mt][3] = ld32bf(p + 8 * SA + 8);
            const __nv_bfloat16* q = sAlo + (mo + mt * 16 + g) * SA + k0 + 2 * t;
            al_[mt][0] = ld32bf(q);
            al_[mt][1] = ld32bf(q + 8 * SA);
            al_[mt][2] = ld32bf(q + 8);
            al_[mt][3] = ld32bf(q + 8 * SA + 8);
        }
#pragma unroll
        for (int nt = 0; nt < 4; nt++) {
            const __nv_bfloat16* p = sBhi + (no + nt * 8 + g) * SA + k0 + 2 * t;
            bh[nt][0] = ld32bf(p);
            bh[nt][1] = ld32bf(p + 8);
            const __nv_bfloat16* q = sBlo + (no + nt * 8 + g) * SA + k0 + 2 * t;
            bl[nt][0] = ld32bf(q);
            bl[nt][1] = ld32bf(q + 8);
        }
#pragma unroll
        for (int mt = 0; mt < MT; mt++)
#pragma unroll
            for (int nt = 0; nt < 4; nt++) {
                mma16816(acc[mt][nt], ah[mt], bh[nt]);
                mma16816(acc[mt][nt], al_[mt], bh[nt]);
                mma16816(acc[mt][nt], ah[mt], bl[nt]);
            }
    }

    // ---- epilogue ----
#pragma unroll
    for (int mt = 0; mt < MT; mt++) {
        int row = m0 + mo + mt * 16 + g;
#pragma unroll
        for (int nt = 0; nt < 4; nt++) {
            int col = n0 + no + nt * 8 + 2 * t;
            float b0 = 0.f, b1 = 0.f;
            if (bias) { b0 = __ldg(&bias[col]); b1 = __ldg(&bias[col + 1]); }
            if (row < M)
                *(float2*)&C[(size_t)row * N + col] =
                    make_float2(acc[mt][nt][0] + b0, acc[mt][nt][1] + b1);
            if (row + 8 < M)
                *(float2*)&C[(size_t)(row + 8) * N + col] =
                    make_float2(acc[mt][nt][2] + b0, acc[mt][nt][3] + b1);
        }
    }
}

// ------------------------- attention logits -------------------------
__global__ void al_kernel(const float* __restrict__ aS, const float* __restrict__ aD) {
    int idx = blockIdx.x * blockDim.x + threadIdx.x;
    if (idx >= NN * NH) return;
    int n = idx >> 2;
    int h = idx & 3;
    const float* hp = &g_hproj[(size_t)n * HC + h * CH];
    const float* as = &aS[h * CH];
    const float* ad = &aD[h * CH];
    float s1 = 0.f, s2 = 0.f;
#pragma unroll
    for (int c = 0; c < CH; c += 4) {
        float4 hv = *(const float4*)&hp[c];
        float4 av = __ldg((const float4*)&as[c]);
        float4 dv = __ldg((const float4*)&ad[c]);
        s1 += hv.x * av.x + hv.y * av.y + hv.z * av.z + hv.w * av.w;
        s2 += hv.x * dv.x + hv.y * dv.y + hv.z * dv.z + hv.w * dv.w;
    }
    g_als[idx] = s1;
    g_ald[idx] = s2;
}

__device__ __forceinline__ float lrelu(float x) { return x > 0.f ? x : 0.2f * x; }

// ------------------------- aggregation (round-3 proven) -------------------------
__global__ void agg_kernel(int skipsel, const float* __restrict__ bias,
                           float* __restrict__ outext, int outsel, int mode) {
    const float* hskip = selbuf_c(skipsel, nullptr);
    float* outp = selbuf(outsel, outext);
    const int WPB = 8;
    __shared__ float sh_alpha[WPB][32][4];
    __shared__ int sh_src[WPB][32];
    int w = threadIdx.x >> 5;
    int lane = threadIdx.x & 31;
    int n = blockIdx.x * WPB + w;
    if (n >= NN) return;
    int beg = g_rowptr[n], end = g_rowptr[n + 1];
    float4 ad = *(const float4*)&g_ald[(size_t)n * 4];

    float mx0 = -1e30f, mx1 = -1e30f, mx2 = -1e30f, mx3 = -1e30f;
    for (int j = beg + lane; j < end; j += 32) {
        int s = __ldg(&g_csr[j]);
        float4 a = __ldg((const float4*)&g_als[(size_t)s * 4]);
        mx0 = fmaxf(mx0, lrelu(a.x + ad.x));
        mx1 = fmaxf(mx1, lrelu(a.y + ad.y));
        mx2 = fmaxf(mx2, lrelu(a.z + ad.z));
        mx3 = fmaxf(mx3, lrelu(a.w + ad.w));
    }
#pragma unroll
    for (int o = 16; o > 0; o >>= 1) {
        mx0 = fmaxf(mx0, __shfl_xor_sync(0xffffffffu, mx0, o));
        mx1 = fmaxf(mx1, __shfl_xor_sync(0xffffffffu, mx1, o));
        mx2 = fmaxf(mx2, __shfl_xor_sync(0xffffffffu, mx2, o));
        mx3 = fmaxf(mx3, __shfl_xor_sync(0xffffffffu, mx3, o));
    }
    float s0 = 0.f, s1 = 0.f, s2 = 0.f, s3 = 0.f;
    for (int j = beg + lane; j < end; j += 32) {
        int s = __ldg(&g_csr[j]);
        float4 a = __ldg((const float4*)&g_als[(size_t)s * 4]);
        s0 += __expf(lrelu(a.x + ad.x) - mx0);
        s1 += __expf(lrelu(a.y + ad.y) - mx1);
        s2 += __expf(lrelu(a.z + ad.z) - mx2);
        s3 += __expf(lrelu(a.w + ad.w) - mx3);
    }
#pragma unroll
    for (int o = 16; o > 0; o >>= 1) {
        s0 += __shfl_xor_sync(0xffffffffu, s0, o);
        s1 += __shfl_xor_sync(0xffffffffu, s1, o);
        s2 += __shfl_xor_sync(0xffffffffu, s2, o);
        s3 += __shfl_xor_sync(0xffffffffu, s3, o);
    }
    float inv0 = 1.f / (s0 + 1e-16f);
    float inv1 = 1.f / (s1 + 1e-16f);
    float inv2 = 1.f / (s2 + 1e-16f);
    float inv3 = 1.f / (s3 + 1e-16f);

    float acc0 = 0.f, acc1 = 0.f, acc2 = 0.f, acc3 = 0.f;
    for (int base = beg; base < end; base += 32) {
        int j = base + lane;
        if (j < end) {
            int sr = g_csr[j];
            sh_src[w][lane] = sr;
            float4 a = __ldg((const float4*)&g_als[(size_t)sr * 4]);
            sh_alpha[w][lane][0] = __expf(lrelu(a.x + ad.x) - mx0) * inv0;
            sh_alpha[w][lane][1] = __expf(lrelu(a.y + ad.y) - mx1) * inv1;
            sh_alpha[w][lane][2] = __expf(lrelu(a.z + ad.z) - mx2) * inv2;
            sh_alpha[w][lane][3] = __expf(lrelu(a.w + ad.w) - mx3) * inv3;
        }
        __syncwarp();
        int cnt = min(32, end - base);
        for (int k = 0; k < cnt; k++) {
            int sr = sh_src[w][k];
            const float* hp = &g_hproj[(size_t)sr * HC];
            float a0 = sh_alpha[w][k][0];
            float a1 = sh_alpha[w][k][1];
            float a2 = sh_alpha[w][k][2];
            float a3 = sh_alpha[w][k][3];
            acc0 += a0 * hp[lane];
            acc1 += a1 * hp[32 + lane];
            acc2 += a2 * hp[64 + lane];
            acc3 += a3 * hp[96 + lane];
        }
        __syncwarp();
    }

    if (mode == 0) {
        float accs[4] = {acc0, acc1, acc2, acc3};
#pragma unroll
        for (int h = 0; h < 4; h++) {
            int c = h * 32 + lane;
            float v = accs[h] + __ldg(&bias[c]) + hskip[(size_t)n * HC + c];
            v = v > 0.f ? v : expm1f(v);
            outp[(size_t)n * HC + c] = v;
        }
    } else {
        float v = 0.25f * (acc0 + acc1 + acc2 + acc3) + __ldg(&bias[lane]) +
                  hskip[(size_t)n * NOUT + lane];
        float ss = v * v;
#pragma unroll
        for (int o = 16; o > 0; o >>= 1) ss += __shfl_xor_sync(0xffffffffu, ss, o);
        float r = sqrtf(ss);
        outp[(size_t)n * NOUT + lane] = v / fmaxf(r, 1e-12f);
    }
}

// ------------------------- launch -------------------------
extern "C" void kernel_launch(void* const* d_in, const int* in_sizes, int n_in,
                              void* d_out, int out_size) {
    const float* x = (const float*)d_in[0];
    const int* ei = (const int*)d_in[1];
    const int* src = ei;
    const int* dst = ei + NE;
    const float* W0 = (const float*)d_in[2];
    const float* aS0 = (const float*)d_in[3];
    const float* aD0 = (const float*)d_in[4];
    const float* b0 = (const float*)d_in[5];
    const float* Ws0 = (const float*)d_in[6];
    const float* bs0 = (const float*)d_in[7];
    const float* W1 = (const float*)d_in[8];
    const float* aS1 = (const float*)d_in[9];
    const float* aD1 = (const float*)d_in[10];
    const float* b1 = (const float*)d_in[11];
    const float* Ws1 = (const float*)d_in[12];
    const float* bs1 = (const float*)d_in[13];
    const float* W2 = (const float*)d_in[14];
    const float* aS2 = (const float*)d_in[15];
    const float* aD2 = (const float*)d_in[16];
    const float* b2 = (const float*)d_in[17];
    const float* Ws2 = (const float*)d_in[18];
    const float* bs2 = (const float*)d_in[19];
    float* out = (float*)d_out;

    // smem: A hi/lo (2*128*136*2B) + B hi/lo (2*BN*136*2B)
    const int SMEM_BIG = (2 * 128 * 136 + 2 * 128 * 136) * 2;   // 139264
    const int SMEM_SMALL = (2 * 128 * 136 + 2 * 32 * 136) * 2;  // 87040
    cudaFuncSetAttribute(bgemm_kernel<128, 64>, cudaFuncAttributeMaxDynamicSharedMemorySize, SMEM_BIG);
    cudaFuncSetAttribute(bgemm_kernel<32, 16>, cudaFuncAttributeMaxDynamicSharedMemorySize, SMEM_SMALL);

    // ---- CSR build ----
    zero_kernel<<<(NN + 255) / 256, 256>>>();
    count_kernel<<<(NE + 255) / 256, 256>>>(dst);
    scan_kernel<<<1, 1024>>>();
    scatter_kernel<<<(NE + 255) / 256, 256>>>(src, dst);

    dim3 gg(1, (NN + 127) / 128);
    int aggBlocks = (NN + 7) / 8;

    // ---- layer 0 ----
    bgemm_kernel<128, 64><<<gg, 256, SMEM_BIG>>>(x, SEL_EXT, W0, nullptr, nullptr, SEL_HPROJ, NN, HC);
    bgemm_kernel<128, 64><<<gg, 256, SMEM_BIG>>>(x, SEL_EXT, Ws0, bs0, nullptr, SEL_HSKIP, NN, HC);
    al_kernel<<<(NN * NH + 255) / 256, 256>>>(aS0, aD0);
    agg_kernel<<<aggBlocks, 256>>>(SEL_HSKIP, b0, nullptr, SEL_FEAT1, 0);

    // ---- layer 1 ----
    bgemm_kernel<128, 64><<<gg, 256, SMEM_BIG>>>(nullptr, SEL_FEAT1, W1, nullptr, nullptr, SEL_HPROJ, NN, HC);
    bgemm_kernel<128, 64><<<gg, 256, SMEM_BIG>>>(nullptr, SEL_FEAT1, Ws1, bs1, nullptr, SEL_HSKIP, NN, HC);
    al_kernel<<<(NN * NH + 255) / 256, 256>>>(aS1, aD1);
    agg_kernel<<<aggBlocks, 256>>>(SEL_HSKIP, b1, nullptr, SEL_FEAT2, 0);

    // ---- layer 2 ----
    bgemm_kernel<128, 64><<<gg, 256, SMEM_BIG>>>(nullptr, SEL_FEAT2, W2, nullptr, nullptr, SEL_HPROJ, NN, HC);
    bgemm_kernel<32, 16><<<gg, 256, SMEM_SMALL>>>(nullptr, SEL_FEAT2, Ws2, bs2, nullptr, SEL_HSKIP32, NN, NOUT);
    al_kernel<<<(NN * NH + 255) / 256, 256>>>(aS2, aD2);
    agg_kernel<<<aggBlocks, 256>>>(SEL_HSKIP32, b2, out, SEL_EXT, 1);
}

// round 8
// speedup vs baseline: 1.7393x; 1.4114x over previous
#include <cuda_runtime.h>
#include <cuda_bf16.h>
#include <cstdint>

#define NN 50000
#define NE 800000
#define HC 128      // HEADS*HID = 4*32
#define NH 4
#define NOUT 32
#define NTILES 391  // ceil(NN/128)
#define SA 136      // padded bf16 row stride (conflict-free fragment LDS)

// ------------------------- device scratch -------------------------
__device__ float g_hproj[(size_t)NN * HC];
__device__ float g_hskip[(size_t)NN * HC];
__device__ float g_hskip32[(size_t)NN * NOUT];
__device__ float g_als[(size_t)NN * NH];
__device__ float g_ald[(size_t)NN * NH];
__device__ int   g_deg[NN];
__device__ int   g_cursor[NN];
__device__ int   g_rowptr[NN + 1];
__device__ int   g_csr[NE];
// padded bf16 hi/lo operand images
__device__ __nv_bfloat16 g_Ahi[(size_t)NTILES * 128 * SA];
__device__ __nv_bfloat16 g_Alo[(size_t)NTILES * 128 * SA];
__device__ __nv_bfloat16 g_Bhi[256 * SA];
__device__ __nv_bfloat16 g_Blo[256 * SA];

#define SEL_HPROJ   1
#define SEL_HSKIP   2
#define SEL_HSKIP32 5
__device__ __forceinline__ float* selbuf(int sel) {
    switch (sel) {
        case SEL_HPROJ:   return g_hproj;
        case SEL_HSKIP:   return g_hskip;
        default:          return g_hskip32;
    }
}

// ------------------------- CSR build -------------------------
__global__ void zero_kernel() {
    int i = blockIdx.x * blockDim.x + threadIdx.x;
    if (i < NN) { g_deg[i] = 0; g_cursor[i] = 0; }
}
__global__ void count_kernel(const int* __restrict__ dst) {
    int i = blockIdx.x * blockDim.x + threadIdx.x;
    if (i < NE) atomicAdd(&g_deg[dst[i]], 1);
}
// single-block warp-shuffle scan
__global__ void scan_kernel() {
    __shared__ int wsums[32];
    __shared__ int carry;
    int tid = threadIdx.x, lane = tid & 31, wid = tid >> 5;
    if (tid == 0) carry = 0;
    __syncthreads();
    for (int base = 0; base < NN; base += 1024) {
        int i = base + tid;
        int v = (i < NN) ? g_deg[i] : 0;
        int x = v;
#pragma unroll
        for (int o = 1; o < 32; o <<= 1) {
            int y = __shfl_up_sync(0xffffffffu, x, o);
            if (lane >= o) x += y;
        }
        if (lane == 31) wsums[wid] = x;
        __syncthreads();
        if (wid == 0) {
            int s = wsums[lane];
#pragma unroll
            for (int o = 1; o < 32; o <<= 1) {
                int y = __shfl_up_sync(0xffffffffu, s, o);
                if (lane >= o) s += y;
            }
            wsums[lane] = s;
        }
        __syncthreads();
        int wpre = (wid == 0) ? 0 : wsums[wid - 1];
        if (i < NN) g_rowptr[i] = x + wpre + carry - v;
        __syncthreads();
        if (tid == 0) carry += wsums[31];
        __syncthreads();
    }
    if (threadIdx.x == 0) g_rowptr[NN] = carry;
}
__global__ void scatter_kernel(const int* __restrict__ src, const int* __restrict__ dst) {
    int i = blockIdx.x * blockDim.x + threadIdx.x;
    if (i < NE) {
        int d = dst[i];
        int pos = g_rowptr[d] + atomicAdd(&g_cursor[d], 1);
        g_csr[pos] = src[i];
    }
}

// ------------------------- operand image conversion -------------------------
__global__ void convA_kernel(const float* __restrict__ src) {
    int idx = blockIdx.x * blockDim.x + threadIdx.x;
    if (idx >= NTILES * 128 * 128) return;
    int n = idx >> 7, k = idx & 127;
    float v = (n < NN) ? src[(size_t)n * 128 + k] : 0.f;
    size_t a = (size_t)n * SA + k;
    __nv_bfloat16 hi = __float2bfloat16(v);
    g_Ahi[a] = hi;
    g_Alo[a] = __float2bfloat16(v - __bfloat162float(hi));
}
// B image rows = output col n ([n][k] layout): n<128 -> W[k,n]; else Ws[k,n-128]
__global__ void convB_kernel(const float* __restrict__ W, const float* __restrict__ Ws,
                             int ns, int n_tot) {
    int idx = blockIdx.x * blockDim.x + threadIdx.x;
    if (idx >= n_tot * 128) return;
    int n = idx >> 7, k = idx & 127;
    float v = (n < 128) ? W[(size_t)k * 128 + n] : Ws[(size_t)k * ns + (n - 128)];
    size_t a = (size_t)n * SA + k;
    __nv_bfloat16 hi = __float2bfloat16(v);
    g_Bhi[a] = hi;
    g_Blo[a] = __float2bfloat16(v - __bfloat162float(hi));
}

// ------------------------- bf16 split HMMA GEMM -------------------------
__device__ __forceinline__ void mma16816(float* c, const uint32_t* a, const uint32_t* b) {
    asm volatile(
        "mma.sync.aligned.m16n8k16.row.col.f32.bf16.bf16.f32 "
        "{%0,%1,%2,%3}, {%4,%5,%6,%7}, {%8,%9}, {%0,%1,%2,%3};"
        : "+f"(c[0]), "+f"(c[1]), "+f"(c[2]), "+f"(c[3])
        : "r"(a[0]), "r"(a[1]), "r"(a[2]), "r"(a[3]), "r"(b[0]), "r"(b[1]));
}
__device__ __forceinline__ uint32_t ld32bf(const __nv_bfloat16* p) {
    return *(const uint32_t*)p;
}

// blockIdx.x selects parameter set (dual launch shares the A tile via L2).
template <int BN, int WM>
__global__ void __launch_bounds__(256) bgemm_kernel(
    const float* __restrict__ bias0, const float* __restrict__ bias1,
    int Csel0, int Csel1, int N0, int N1, int bOff0, int bOff1,
    const float* __restrict__ aS, const float* __restrict__ aD, int doAL0, int M) {
    const float* bias = (blockIdx.x == 0) ? bias0 : bias1;
    float* C = selbuf((blockIdx.x == 0) ? Csel0 : Csel1);
    int N = (blockIdx.x == 0) ? N0 : N1;
    int bOff = (blockIdx.x == 0) ? bOff0 : bOff1;
    bool doAL = (blockIdx.x == 0) && doAL0;

    constexpr int MT = WM / 16;
    constexpr int WARPS_N = BN / 32;
    extern __shared__ __nv_bfloat16 sm[];
    __nv_bfloat16* sAhi = sm;
    __nv_bfloat16* sAlo = sm + 128 * SA;
    __nv_bfloat16* sBhi = sm + 2 * 128 * SA;
    __nv_bfloat16* sBlo = sBhi + BN * SA;

    int tid = threadIdx.x;
    int lane = tid & 31, w = tid >> 5;
    int m0 = blockIdx.y * 128;

    // ---- stage: pure uint4 copies of pre-converted images ----
    {
        const uint4* gAh = (const uint4*)(g_Ahi + (size_t)blockIdx.y * 128 * SA);
        const uint4* gAl = (const uint4*)(g_Alo + (size_t)blockIdx.y * 128 * SA);
        uint4* dAh = (uint4*)sAhi;
        uint4* dAl = (uint4*)sAlo;
#pragma unroll
        for (int i = tid; i < 128 * SA / 8; i += 256) { dAh[i] = gAh[i]; dAl[i] = gAl[i]; }
        const uint4* gBh = (const uint4*)(g_Bhi + bOff);
        const uint4* gBl = (const uint4*)(g_Blo + bOff);
        uint4* dBh = (uint4*)sBhi;
        uint4* dBl = (uint4*)sBlo;
        for (int i = tid; i < BN * SA / 8; i += 256) { dBh[i] = gBh[i]; dBl[i] = gBl[i]; }
    }
    __syncthreads();

    int wm = w / WARPS_N, wn = w % WARPS_N;
    int mo = wm * WM, no = wn * 32;
    int g = lane >> 2, t = lane & 3;

    float acc[MT][4][4] = {};

#pragma unroll
    for (int k0 = 0; k0 < 128; k0 += 16) {
        uint32_t ah[MT][4], al_[MT][4], bh[4][2], bl[4][2];
#pragma unroll
        for (int mt = 0; mt < MT; mt++) {
            const __nv_bfloat16* p = sAhi + (mo + mt * 16 + g) * SA + k0 + 2 * t;
            ah[mt][0] = ld32bf(p);
            ah[mt][1] = ld32bf(p + 8 * SA);
            ah[mt][2] = ld32bf(p + 8);
            ah[mt][3] = ld32bf(p + 8 * SA + 8);
            const __nv_bfloat16* q = sAlo + (mo + mt * 16 + g) * SA + k0 + 2 * t;
            al_[mt][0] = ld32bf(q);
            al_[mt][1] = ld32bf(q + 8 * SA);
            al_[mt][2] = ld32bf(q + 8);
            al_[mt][3] = ld32bf(q + 8 * SA + 8);
        }
#pragma unroll
        for (int nt = 0; nt < 4; nt++) {
            const __nv_bfloat16* p = sBhi + (no + nt * 8 + g) * SA + k0 + 2 * t;
            bh[nt][0] = ld32bf(p);
            bh[nt][1] = ld32bf(p + 8);
            const __nv_bfloat16* q = sBlo + (no + nt * 8 + g) * SA + k0 + 2 * t;
            bl[nt][0] = ld32bf(q);
            bl[nt][1] = ld32bf(q + 8);
        }
#pragma unroll
        for (int mt = 0; mt < MT; mt++)
#pragma unroll
            for (int nt = 0; nt < 4; nt++) {
                mma16816(acc[mt][nt], ah[mt], bh[nt]);
                mma16816(acc[mt][nt], al_[mt], bh[nt]);
                mma16816(acc[mt][nt], ah[mt], bl[nt]);
            }
    }

    // ---- epilogue: store C (+bias) ----
#pragma unroll
    for (int mt = 0; mt < MT; mt++) {
        int row = m0 + mo + mt * 16 + g;
#pragma unroll
        for (int nt = 0; nt < 4; nt++) {
            int col = no + nt * 8 + 2 * t;
            float b0 = 0.f, b1 = 0.f;
            if (bias) { b0 = __ldg(&bias[col]); b1 = __ldg(&bias[col + 1]); }
            if (row < M)
                *(float2*)&C[(size_t)row * N + col] =
                    make_float2(acc[mt][nt][0] + b0, acc[mt][nt][1] + b1);
            if (row + 8 < M)
                *(float2*)&C[(size_t)(row + 8) * N + col] =
                    make_float2(acc[mt][nt][2] + b0, acc[mt][nt][3] + b1);
        }
    }

    // ---- fused attention logits (proj pass only): warp wn owns head wn ----
    if (doAL) {
        float sS[MT][2], sD[MT][2];
#pragma unroll
        for (int mt = 0; mt < MT; mt++) { sS[mt][0] = sS[mt][1] = sD[mt][0] = sD[mt][1] = 0.f; }
#pragma unroll
        for (int nt = 0; nt < 4; nt++) {
            int col = no + nt * 8 + 2 * t;
            float c0s = __ldg(&aS[col]), c1s = __ldg(&aS[col + 1]);
            float c0d = __ldg(&aD[col]), c1d = __ldg(&aD[col + 1]);
#pragma unroll
            for (int mt = 0; mt < MT; mt++) {
                sS[mt][0] += acc[mt][nt][0] * c0s + acc[mt][nt][1] * c1s;
                sS[mt][1] += acc[mt][nt][2] * c0s + acc[mt][nt][3] * c1s;
                sD[mt][0] += acc[mt][nt][0] * c0d + acc[mt][nt][1] * c1d;
                sD[mt][1] += acc[mt][nt][2] * c0d + acc[mt][nt][3] * c1d;
            }
        }
        // reduce over the 4-lane t-group (lanes g*4+t)
#pragma unroll
        for (int mt = 0; mt < MT; mt++)
#pragma unroll
            for (int half = 0; half < 2; half++) {
                sS[mt][half] += __shfl_xor_sync(0xffffffffu, sS[mt][half], 1);
                sS[mt][half] += __shfl_xor_sync(0xffffffffu, sS[mt][half], 2);
                sD[mt][half] += __shfl_xor_sync(0xffffffffu, sD[mt][half], 1);
                sD[mt][half] += __shfl_xor_sync(0xffffffffu, sD[mt][half], 2);
            }
        if (t == 0) {
#pragma unroll
            for (int mt = 0; mt < MT; mt++) {
                int row = m0 + mo + mt * 16 + g;
                if (row < M) { g_als[(size_t)row * 4 + wn] = sS[mt][0]; g_ald[(size_t)row * 4 + wn] = sD[mt][0]; }
                if (row + 8 < M) { g_als[(size_t)(row + 8) * 4 + wn] = sS[mt][1]; g_ald[(size_t)(row + 8) * 4 + wn] = sD[mt][1]; }
            }
        }
    }
}

__device__ __forceinline__ float lrelu(float x) { return x > 0.f ? x : 0.2f * x; }

// ------------------------- aggregation -------------------------
// mode 0: concat+bias+skip+ELU -> next layer's A image (bf16 hi/lo)
// mode 1: head-mean + bias + skip + L2-normalize -> out[N,32]
__global__ void agg_kernel(int skipsel, const float* __restrict__ bias,
                           float* __restrict__ outp, int mode) {
    const float* hskip = selbuf(skipsel);
    const int WPB = 8;
    __shared__ float sh_alpha[WPB][32][4];
    __shared__ int sh_src[WPB][32];
    int w = threadIdx.x >> 5;
    int lane = threadIdx.x & 31;
    int n = blockIdx.x * WPB + w;
    if (n >= NN) return;
    int beg = g_rowptr[n], end = g_rowptr[n + 1];
    float4 ad = *(const float4*)&g_ald[(size_t)n * 4];

    float mx0 = -1e30f, mx1 = -1e30f, mx2 = -1e30f, mx3 = -1e30f;
    for (int j = beg + lane; j < end; j += 32) {
        int s = __ldg(&g_csr[j]);
        float4 a = __ldg((const float4*)&g_als[(size_t)s * 4]);
        mx0 = fmaxf(mx0, lrelu(a.x + ad.x));
        mx1 = fmaxf(mx1, lrelu(a.y + ad.y));
        mx2 = fmaxf(mx2, lrelu(a.z + ad.z));
        mx3 = fmaxf(mx3, lrelu(a.w + ad.w));
    }
#pragma unroll
    for (int o = 16; o > 0; o >>= 1) {
        mx0 = fmaxf(mx0, __shfl_xor_sync(0xffffffffu, mx0, o));
        mx1 = fmaxf(mx1, __shfl_xor_sync(0xffffffffu, mx1, o));
        mx2 = fmaxf(mx2, __shfl_xor_sync(0xffffffffu, mx2, o));
        mx3 = fmaxf(mx3, __shfl_xor_sync(0xffffffffu, mx3, o));
    }
    float s0 = 0.f, s1 = 0.f, s2 = 0.f, s3 = 0.f;
    for (int j = beg + lane; j < end; j += 32) {
        int s = __ldg(&g_csr[j]);
        float4 a = __ldg((const float4*)&g_als[(size_t)s * 4]);
        s0 += __expf(lrelu(a.x + ad.x) - mx0);
        s1 += __expf(lrelu(a.y + ad.y) - mx1);
        s2 += __expf(lrelu(a.z + ad.z) - mx2);
        s3 += __expf(lrelu(a.w + ad.w) - mx3);
    }
#pragma unroll
    for (int o = 16; o > 0; o >>= 1) {
        s0 += __shfl_xor_sync(0xffffffffu, s0, o);
        s1 += __shfl_xor_sync(0xffffffffu, s1, o);
        s2 += __shfl_xor_sync(0xffffffffu, s2, o);
        s3 += __shfl_xor_sync(0xffffffffu, s3, o);
    }
    float inv0 = 1.f / (s0 + 1e-16f);
    float inv1 = 1.f / (s1 + 1e-16f);
    float inv2 = 1.f / (s2 + 1e-16f);
    float inv3 = 1.f / (s3 + 1e-16f);

    float acc0 = 0.f, acc1 = 0.f, acc2 = 0.f, acc3 = 0.f;
    for (int base = beg; base < end; base += 32) {
        int j = base + lane;
        if (j < end) {
            int sr = g_csr[j];
            sh_src[w][lane] = sr;
            float4 a = __ldg((const float4*)&g_als[(size_t)sr * 4]);
            sh_alpha[w][lane][0] = __expf(lrelu(a.x + ad.x) - mx0) * inv0;
            sh_alpha[w][lane][1] = __expf(lrelu(a.y + ad.y) - mx1) * inv1;
            sh_alpha[w][lane][2] = __expf(lrelu(a.z + ad.z) - mx2) * inv2;
            sh_alpha[w][lane][3] = __expf(lrelu(a.w + ad.w) - mx3) * inv3;
        }
        __syncwarp();
        int cnt = min(32, end - base);
        for (int k = 0; k < cnt; k++) {
            int sr = sh_src[w][k];
            const float* hp = &g_hproj[(size_t)sr * HC];
            float a0 = sh_alpha[w][k][0];
            float a1 = sh_alpha[w][k][1];
            float a2 = sh_alpha[w][k][2];
            float a3 = sh_alpha[w][k][3];
            acc0 += a0 * hp[lane];
            acc1 += a1 * hp[32 + lane];
            acc2 += a2 * hp[64 + lane];
            acc3 += a3 * hp[96 + lane];
        }
        __syncwarp();
    }

    if (mode == 0) {
        float accs[4] = {acc0, acc1, acc2, acc3};
#pragma unroll
        for (int h = 0; h < 4; h++) {
            int c = h * 32 + lane;
            float v = accs[h] + __ldg(&bias[c]) + hskip[(size_t)n * HC + c];
            v = v > 0.f ? v : expm1f(v);
            size_t a = (size_t)n * SA + c;
            __nv_bfloat16 hi = __float2bfloat16(v);
            g_Ahi[a] = hi;
            g_Alo[a] = __float2bfloat16(v - __bfloat162float(hi));
        }
    } else {
        float v = 0.25f * (acc0 + acc1 + acc2 + acc3) + __ldg(&bias[lane]) +
                  hskip[(size_t)n * NOUT + lane];
        float ss = v * v;
#pragma unroll
        for (int o = 16; o > 0; o >>= 1) ss += __shfl_xor_sync(0xffffffffu, ss, o);
        float r = sqrtf(ss);
        outp[(size_t)n * NOUT + lane] = v / fmaxf(r, 1e-12f);
    }
}

// ------------------------- launch -------------------------
extern "C" void kernel_launch(void* const* d_in, const int* in_sizes, int n_in,
                              void* d_out, int out_size) {
    const float* x = (const float*)d_in[0];
    const int* ei = (const int*)d_in[1];
    const int* src = ei;
    const int* dst = ei + NE;
    const float* W0 = (const float*)d_in[2];
    const float* aS0 = (const float*)d_in[3];
    const float* aD0 = (const float*)d_in[4];
    const float* b0 = (const float*)d_in[5];
    const float* Ws0 = (const float*)d_in[6];
    const float* bs0 = (const float*)d_in[7];
    const float* W1 = (const float*)d_in[8];
    const float* aS1 = (const float*)d_in[9];
    const float* aD1 = (const float*)d_in[10];
    const float* b1 = (const float*)d_in[11];
    const float* Ws1 = (const float*)d_in[12];
    const float* bs1 = (const float*)d_in[13];
    const float* W2 = (const float*)d_in[14];
    const float* aS2 = (const float*)d_in[15];
    const float* aD2 = (const float*)d_in[16];
    const float* b2 = (const float*)d_in[17];
    const float* Ws2 = (const float*)d_in[18];
    const float* bs2 = (const float*)d_in[19];
    float* out = (float*)d_out;

    const int SMEM_BIG = (2 * 128 * SA + 2 * 128 * SA) * 2;   // 139264
    const int SMEM_SMALL = (2 * 128 * SA + 2 * 32 * SA) * 2;  // 87040
    cudaFuncSetAttribute(bgemm_kernel<128, 64>, cudaFuncAttributeMaxDynamicSharedMemorySize, SMEM_BIG);
    cudaFuncSetAttribute(bgemm_kernel<32, 16>, cudaFuncAttributeMaxDynamicSharedMemorySize, SMEM_SMALL);

    // ---- CSR build ----
    zero_kernel<<<(NN + 255) / 256, 256>>>();
    count_kernel<<<(NE + 255) / 256, 256>>>(dst);
    scan_kernel<<<1, 1024>>>();
    scatter_kernel<<<(NE + 255) / 256, 256>>>(src, dst);

    dim3 gdual(2, NTILES);
    dim3 gsingle(1, NTILES);
    int aggBlocks = (NN + 7) / 8;
    int convABlocks = (NTILES * 128 * 128) / 256;

    // ---- layer 0 ----
    convA_kernel<<<convABlocks, 256>>>(x);
    convB_kernel<<<(256 * 128 + 255) / 256, 256>>>(W0, Ws0, 128, 256);
    bgemm_kernel<128, 64><<<gdual, 256, SMEM_BIG>>>(
        nullptr, bs0, SEL_HPROJ, SEL_HSKIP, HC, HC, 0, 128 * SA, aS0, aD0, 1, NN);
    agg_kernel<<<aggBlocks, 256>>>(SEL_HSKIP, b0, nullptr, 0);

    // ---- layer 1 ----
    convB_kernel<<<(256 * 128 + 255) / 256, 256>>>(W1, Ws1, 128, 256);
    bgemm_kernel<128, 64><<<gdual, 256, SMEM_BIG>>>(
        nullptr, bs1, SEL_HPROJ, SEL_HSKIP, HC, HC, 0, 128 * SA, aS1, aD1, 1, NN);
    agg_kernel<<<aggBlocks, 256>>>(SEL_HSKIP, b1, nullptr, 0);

    // ---- layer 2 ----
    convB_kernel<<<(160 * 128 + 255) / 256, 256>>>(W2, Ws2, 32, 160);
    bgemm_kernel<128, 64><<<gsingle, 256, SMEM_BIG>>>(
        nullptr, nullptr, SEL_HPROJ, SEL_HPROJ, HC, HC, 0, 0, aS2, aD2, 1, NN);
    bgemm_kernel<32, 16><<<gsingle, 256, SMEM_SMALL>>>(
        bs2, bs2, SEL_HSKIP32, SEL_HSKIP32, NOUT, NOUT, 128 * SA, 128 * SA, nullptr, nullptr, 0, NN);
    agg_kernel<<<aggBlocks, 256>>>(SEL_HSKIP32, b2, out, 1);
}

// round 9
// speedup vs baseline: 2.0959x; 1.2051x over previous
#include <cuda_runtime.h>
#include <cuda_bf16.h>
#include <cstdint>

#define NN 50000
#define NE 800000
#define HC 128      // HEADS*HID = 4*32
#define NH 4
#define NOUT 32
#define NTILES 391  // ceil(NN/128)
#define SA 136      // padded bf16 row stride

// ------------------------- device scratch -------------------------
__device__ float g_hproj[(size_t)NN * HC];
__device__ float g_hskip[(size_t)NN * HC];
__device__ float g_hskip32[(size_t)NN * NOUT];
__device__ float g_als[(size_t)NN * NH];
__device__ float g_ald[(size_t)NN * NH];
__device__ int   g_deg[NN];
__device__ int   g_cursor[NN];
__device__ int   g_rowptr[NN + 1];
__device__ int   g_csr[NE];
__device__ __nv_bfloat16 g_Ahi[(size_t)NTILES * 128 * SA];
__device__ __nv_bfloat16 g_Alo[(size_t)NTILES * 128 * SA];
__device__ __nv_bfloat16 g_Bhi[256 * SA];
__device__ __nv_bfloat16 g_Blo[256 * SA];

#define SEL_HSKIP   2
#define SEL_HSKIP32 5
__device__ __forceinline__ const float* selbuf(int sel) {
    return (sel == SEL_HSKIP) ? g_hskip : g_hskip32;
}

// ------------------------- CSR build -------------------------
__global__ void zero_kernel() {
    int i = blockIdx.x * blockDim.x + threadIdx.x;
    if (i < NN) g_deg[i] = 0;
}
__global__ void count_kernel(const int* __restrict__ dst) {
    int i = blockIdx.x * blockDim.x + threadIdx.x;
    if (i < NE) atomicAdd(&g_deg[dst[i]], 1);
}
// single-block warp-shuffle scan; also seeds g_cursor with rowptr
__global__ void scan_kernel() {
    __shared__ int wsums[32];
    __shared__ int carry;
    int tid = threadIdx.x, lane = tid & 31, wid = tid >> 5;
    if (tid == 0) carry = 0;
    __syncthreads();
    for (int base = 0; base < NN; base += 1024) {
        int i = base + tid;
        int v = (i < NN) ? g_deg[i] : 0;
        int x = v;
#pragma unroll
        for (int o = 1; o < 32; o <<= 1) {
            int y = __shfl_up_sync(0xffffffffu, x, o);
            if (lane >= o) x += y;
        }
        if (lane == 31) wsums[wid] = x;
        __syncthreads();
        if (wid == 0) {
            int s = wsums[lane];
#pragma unroll
            for (int o = 1; o < 32; o <<= 1) {
                int y = __shfl_up_sync(0xffffffffu, s, o);
                if (lane >= o) s += y;
            }
            wsums[lane] = s;
        }
        __syncthreads();
        int wpre = (wid == 0) ? 0 : wsums[wid - 1];
        if (i < NN) {
            int rp = x + wpre + carry - v;
            g_rowptr[i] = rp;
            g_cursor[i] = rp;
        }
        __syncthreads();
        if (tid == 0) carry += wsums[31];
        __syncthreads();
    }
    if (threadIdx.x == 0) g_rowptr[NN] = carry;
}
__global__ void scatter_kernel(const int* __restrict__ src, const int* __restrict__ dst) {
    int i = blockIdx.x * blockDim.x + threadIdx.x;
    if (i < NE) {
        int pos = atomicAdd(&g_cursor[dst[i]], 1);
        g_csr[pos] = src[i];
    }
}

// ------------------------- operand image conversion -------------------------
__device__ __forceinline__ uint32_t pack_bf2(__nv_bfloat16 a, __nv_bfloat16 b) {
    return ((uint32_t)__bfloat16_as_ushort(b) << 16) | __bfloat16_as_ushort(a);
}
__global__ void convA_kernel(const float* __restrict__ src) {
    int idx = blockIdx.x * blockDim.x + threadIdx.x;
    if (idx >= NTILES * 128 * 32) return;
    int n = idx >> 5, c4 = (idx & 31) * 4;
    float4 v = (n < NN) ? *(const float4*)&src[(size_t)n * 128 + c4]
                        : make_float4(0.f, 0.f, 0.f, 0.f);
    float vv[4] = {v.x, v.y, v.z, v.w};
    __nv_bfloat16 hi[4], lo[4];
#pragma unroll
    for (int e = 0; e < 4; e++) {
        hi[e] = __float2bfloat16(vv[e]);
        lo[e] = __float2bfloat16(vv[e] - __bfloat162float(hi[e]));
    }
    size_t a = (size_t)n * SA + c4;
    *(uint2*)&g_Ahi[a] = make_uint2(pack_bf2(hi[0], hi[1]), pack_bf2(hi[2], hi[3]));
    *(uint2*)&g_Alo[a] = make_uint2(pack_bf2(lo[0], lo[1]), pack_bf2(lo[2], lo[3]));
}
// B image rows = output col n ([n][k]); n<128 -> W[k,n]; [128,nv) -> Ws[k,n-128]; [nv,nst) -> 0
__global__ void convB_kernel(const float* __restrict__ W, const float* __restrict__ Ws,
                             int ns, int n_valid, int n_stage) {
    int idx = blockIdx.x * blockDim.x + threadIdx.x;
    if (idx >= n_stage * 128) return;
    int n = idx >> 7, k = idx & 127;
    float v = 0.f;
    if (n < 128) v = W[(size_t)k * 128 + n];
    else if (n < n_valid) v = Ws[(size_t)k * ns + (n - 128)];
    size_t a = (size_t)n * SA + k;
    __nv_bfloat16 hi = __float2bfloat16(v);
    g_Bhi[a] = hi;
    g_Blo[a] = __float2bfloat16(v - __bfloat162float(hi));
}

// ------------------------- bf16 split HMMA GEMM (64-col panels, 2 CTA/SM) -------------------------
__device__ __forceinline__ void mma16816(float* c, const uint32_t* a, const uint32_t* b) {
    asm volatile(
        "mma.sync.aligned.m16n8k16.row.col.f32.bf16.bf16.f32 "
        "{%0,%1,%2,%3}, {%4,%5,%6,%7}, {%8,%9}, {%0,%1,%2,%3};"
        : "+f"(c[0]), "+f"(c[1]), "+f"(c[2]), "+f"(c[3])
        : "r"(a[0]), "r"(a[1]), "r"(a[2]), "r"(a[3]), "r"(b[0]), "r"(b[1]));
}
__device__ __forceinline__ uint32_t ld32bf(const __nv_bfloat16* p) {
    return *(const uint32_t*)p;
}

// blockIdx.x = panel p. l2mode 0: p0,p1 proj / p2,p3 skip(128-wide). l2mode 1: p0,p1 proj / p2 skip32.
__global__ void __launch_bounds__(256, 2) bgemm64_kernel(
    const float* __restrict__ bias_skip,
    const float* __restrict__ aS, const float* __restrict__ aD, int l2mode, int M) {
    int p = blockIdx.x;
    int bOff, colOff, N, ncols;
    float* C;
    const float* bias;
    bool doAL;
    if (p < 2) {  // proj panels
        bOff = p * 64 * SA; C = g_hproj; colOff = p * 64; N = 128; ncols = 64;
        bias = nullptr; doAL = true;
    } else if (!l2mode) {  // skip panels, layers 0/1
        bOff = p * 64 * SA; C = g_hskip; colOff = (p - 2) * 64; N = 128; ncols = 64;
        bias = bias_skip + colOff; doAL = false;
    } else {  // skip panel, layer 2
        bOff = 128 * SA; C = g_hskip32; colOff = 0; N = 32; ncols = 32;
        bias = bias_skip; doAL = false;
    }

    extern __shared__ __nv_bfloat16 sm[];
    __nv_bfloat16* sAhi = sm;
    __nv_bfloat16* sAlo = sm + 128 * SA;
    __nv_bfloat16* sBhi = sm + 2 * 128 * SA;
    __nv_bfloat16* sBlo = sBhi + 64 * SA;

    int tid = threadIdx.x;
    int lane = tid & 31, w = tid >> 5;
    int m0 = blockIdx.y * 128;

    // stage: pure uint4 copies
    {
        const uint4* gAh = (const uint4*)(g_Ahi + (size_t)blockIdx.y * 128 * SA);
        const uint4* gAl = (const uint4*)(g_Alo + (size_t)blockIdx.y * 128 * SA);
        uint4* dAh = (uint4*)sAhi;
        uint4* dAl = (uint4*)sAlo;
#pragma unroll
        for (int i = tid; i < 128 * SA / 8; i += 256) { dAh[i] = gAh[i]; dAl[i] = gAl[i]; }
        const uint4* gBh = (const uint4*)(g_Bhi + bOff);
        const uint4* gBl = (const uint4*)(g_Blo + bOff);
        uint4* dBh = (uint4*)sBhi;
        uint4* dBl = (uint4*)sBlo;
#pragma unroll
        for (int i = tid; i < 64 * SA / 8; i += 256) { dBh[i] = gBh[i]; dBl[i] = gBl[i]; }
    }
    __syncthreads();

    int wm = w >> 1, wn = w & 1;
    int mo = wm * 32, no = wn * 32;
    int g = lane >> 2, t = lane & 3;

    float acc[2][4][4] = {};

#pragma unroll
    for (int k0 = 0; k0 < 128; k0 += 16) {
        uint32_t ah[2][4], al_[2][4], bh[4][2], bl[4][2];
#pragma unroll
        for (int mt = 0; mt < 2; mt++) {
            const __nv_bfloat16* pp = sAhi + (mo + mt * 16 + g) * SA + k0 + 2 * t;
            ah[mt][0] = ld32bf(pp);
            ah[mt][1] = ld32bf(pp + 8 * SA);
            ah[mt][2] = ld32bf(pp + 8);
            ah[mt][3] = ld32bf(pp + 8 * SA + 8);
            const __nv_bfloat16* q = sAlo + (mo + mt * 16 + g) * SA + k0 + 2 * t;
            al_[mt][0] = ld32bf(q);
            al_[mt][1] = ld32bf(q + 8 * SA);
            al_[mt][2] = ld32bf(q + 8);
            al_[mt][3] = ld32bf(q + 8 * SA + 8);
        }
#pragma unroll
        for (int nt = 0; nt < 4; nt++) {
            const __nv_bfloat16* pp = sBhi + (no + nt * 8 + g) * SA + k0 + 2 * t;
            bh[nt][0] = ld32bf(pp);
            bh[nt][1] = ld32bf(pp + 8);
            const __nv_bfloat16* q = sBlo + (no + nt * 8 + g) * SA + k0 + 2 * t;
            bl[nt][0] = ld32bf(q);
            bl[nt][1] = ld32bf(q + 8);
        }
#pragma unroll
        for (int mt = 0; mt < 2; mt++)
#pragma unroll
            for (int nt = 0; nt < 4; nt++) {
                mma16816(acc[mt][nt], ah[mt], bh[nt]);
                mma16816(acc[mt][nt], al_[mt], bh[nt]);
                mma16816(acc[mt][nt], ah[mt], bl[nt]);
            }
    }

    // epilogue: store C (+bias)
#pragma unroll
    for (int mt = 0; mt < 2; mt++) {
        int row = m0 + mo + mt * 16 + g;
#pragma unroll
        for (int nt = 0; nt < 4; nt++) {
            int cl = no + nt * 8 + 2 * t;
            if (cl >= ncols) continue;
            float b0 = 0.f, b1 = 0.f;
            if (bias) { b0 = __ldg(&bias[cl]); b1 = __ldg(&bias[cl + 1]); }
            if (row < M)
                *(float2*)&C[(size_t)row * N + colOff + cl] =
                    make_float2(acc[mt][nt][0] + b0, acc[mt][nt][1] + b1);
            if (row + 8 < M)
                *(float2*)&C[(size_t)(row + 8) * N + colOff + cl] =
                    make_float2(acc[mt][nt][2] + b0, acc[mt][nt][3] + b1);
        }
    }

    // fused attention logits: warp's 32 cols = head (colOff+no)/32
    if (doAL) {
        int head = (colOff + no) >> 5;
        float sS[2][2], sD[2][2];
#pragma unroll
        for (int mt = 0; mt < 2; mt++) { sS[mt][0] = sS[mt][1] = sD[mt][0] = sD[mt][1] = 0.f; }
#pragma unroll
        for (int nt = 0; nt < 4; nt++) {
            int col = colOff + no + nt * 8 + 2 * t;
            float c0s = __ldg(&aS[col]), c1s = __ldg(&aS[col + 1]);
            float c0d = __ldg(&aD[col]), c1d = __ldg(&aD[col + 1]);
#pragma unroll
            for (int mt = 0; mt < 2; mt++) {
                sS[mt][0] += acc[mt][nt][0] * c0s + acc[mt][nt][1] * c1s;
                sS[mt][1] += acc[mt][nt][2] * c0s + acc[mt][nt][3] * c1s;
                sD[mt][0] += acc[mt][nt][0] * c0d + acc[mt][nt][1] * c1d;
                sD[mt][1] += acc[mt][nt][2] * c0d + acc[mt][nt][3] * c1d;
            }
        }
#pragma unroll
        for (int mt = 0; mt < 2; mt++)
#pragma unroll
            for (int half = 0; half < 2; half++) {
                sS[mt][half] += __shfl_xor_sync(0xffffffffu, sS[mt][half], 1);
                sS[mt][half] += __shfl_xor_sync(0xffffffffu, sS[mt][half], 2);
                sD[mt][half] += __shfl_xor_sync(0xffffffffu, sD[mt][half], 1);
                sD[mt][half] += __shfl_xor_sync(0xffffffffu, sD[mt][half], 2);
            }
        if (t == 0) {
#pragma unroll
            for (int mt = 0; mt < 2; mt++) {
                int row = m0 + mo + mt * 16 + g;
                if (row < M) { g_als[(size_t)row * 4 + head] = sS[mt][0]; g_ald[(size_t)row * 4 + head] = sD[mt][0]; }
                if (row + 8 < M) { g_als[(size_t)(row + 8) * 4 + head] = sS[mt][1]; g_ald[(size_t)(row + 8) * 4 + head] = sD[mt][1]; }
            }
        }
    }
}

__device__ __forceinline__ float lrelu(float x) { return x > 0.f ? x : 0.2f * x; }

// ------------------------- aggregation (2 passes, no-max softmax, float4 gather) -------------------------
__global__ void agg_kernel(int skipsel, const float* __restrict__ bias,
                           float* __restrict__ outp, int mode) {
    const float* hskip = selbuf(skipsel);
    const int WPB = 8;
    __shared__ float sh_alpha[WPB][32][4];
    __shared__ int sh_src[WPB][32];
    int w = threadIdx.x >> 5;
    int lane = threadIdx.x & 31;
    int n = blockIdx.x * WPB + w;
    if (n >= NN) return;
    int beg = g_rowptr[n], end = g_rowptr[n + 1];
    float4 ad = *(const float4*)&g_ald[(size_t)n * 4];

    // pass A: sum of exp (softmax shift-invariant; logits are O(10), no overflow)
    float s0 = 0.f, s1 = 0.f, s2 = 0.f, s3 = 0.f;
    for (int j = beg + lane; j < end; j += 32) {
        int s = __ldg(&g_csr[j]);
        float4 a = __ldg((const float4*)&g_als[(size_t)s * 4]);
        s0 += __expf(lrelu(a.x + ad.x));
        s1 += __expf(lrelu(a.y + ad.y));
        s2 += __expf(lrelu(a.z + ad.z));
        s3 += __expf(lrelu(a.w + ad.w));
    }
#pragma unroll
    for (int o = 16; o > 0; o >>= 1) {
        s0 += __shfl_xor_sync(0xffffffffu, s0, o);
        s1 += __shfl_xor_sync(0xffffffffu, s1, o);
        s2 += __shfl_xor_sync(0xffffffffu, s2, o);
        s3 += __shfl_xor_sync(0xffffffffu, s3, o);
    }
    float inv0 = 1.f / (s0 + 1e-16f);
    float inv1 = 1.f / (s1 + 1e-16f);
    float inv2 = 1.f / (s2 + 1e-16f);
    float inv3 = 1.f / (s3 + 1e-16f);

    // pass B: weighted float4 gather; lane owns cols 4L..4L+3 (head L>>3)
    int hsel = lane >> 3;
    float4 acc = make_float4(0.f, 0.f, 0.f, 0.f);
    for (int base = beg; base < end; base += 32) {
        int j = base + lane;
        if (j < end) {
            int sr = g_csr[j];
            sh_src[w][lane] = sr;
            float4 a = __ldg((const float4*)&g_als[(size_t)sr * 4]);
            sh_alpha[w][lane][0] = __expf(lrelu(a.x + ad.x)) * inv0;
            sh_alpha[w][lane][1] = __expf(lrelu(a.y + ad.y)) * inv1;
            sh_alpha[w][lane][2] = __expf(lrelu(a.z + ad.z)) * inv2;
            sh_alpha[w][lane][3] = __expf(lrelu(a.w + ad.w)) * inv3;
        }
        __syncwarp();
        int cnt = min(32, end - base);
#pragma unroll 4
        for (int k = 0; k < cnt; k++) {
            int sr = sh_src[w][k];
            float av = sh_alpha[w][k][hsel];
            float4 hv = *(const float4*)&g_hproj[(size_t)sr * HC + 4 * lane];
            acc.x += av * hv.x;
            acc.y += av * hv.y;
            acc.z += av * hv.z;
            acc.w += av * hv.w;
        }
        __syncwarp();
    }

    if (mode == 0) {
        float4 bb = __ldg((const float4*)&bias[4 * lane]);
        float4 sk = *(const float4*)&hskip[(size_t)n * HC + 4 * lane];
        float v[4] = {acc.x + bb.x + sk.x, acc.y + bb.y + sk.y,
                      acc.z + bb.z + sk.z, acc.w + bb.w + sk.w};
        __nv_bfloat16 hi[4], lo[4];
#pragma unroll
        for (int e = 0; e < 4; e++) {
            v[e] = v[e] > 0.f ? v[e] : expm1f(v[e]);
            hi[e] = __float2bfloat16(v[e]);
            lo[e] = __float2bfloat16(v[e] - __bfloat162float(hi[e]));
        }
        size_t a = (size_t)n * SA + 4 * lane;
        *(uint2*)&g_Ahi[a] = make_uint2(pack_bf2(hi[0], hi[1]), pack_bf2(hi[2], hi[3]));
        *(uint2*)&g_Alo[a] = make_uint2(pack_bf2(lo[0], lo[1]), pack_bf2(lo[2], lo[3]));
    } else {
        // head-mean: sum over lanes {L, L^8, L^16, L^24}
#pragma unroll
        for (int o = 8; o <= 16; o <<= 1) {
            acc.x += __shfl_xor_sync(0xffffffffu, acc.x, o);
            acc.y += __shfl_xor_sync(0xffffffffu, acc.y, o);
            acc.z += __shfl_xor_sync(0xffffffffu, acc.z, o);
            acc.w += __shfl_xor_sync(0xffffffffu, acc.w, o);
        }
        int cc = 4 * (lane & 7);
        float4 bb = __ldg((const float4*)&bias[cc]);
        float4 sk = *(const float4*)&hskip[(size_t)n * NOUT + cc];
        float v[4] = {0.25f * acc.x + bb.x + sk.x, 0.25f * acc.y + bb.y + sk.y,
                      0.25f * acc.z + bb.z + sk.z, 0.25f * acc.w + bb.w + sk.w};
        float ss = v[0] * v[0] + v[1] * v[1] + v[2] * v[2] + v[3] * v[3];
#pragma unroll
        for (int o = 1; o <= 4; o <<= 1) ss += __shfl_xor_sync(0xffffffffu, ss, o);
        float r = fmaxf(sqrtf(ss), 1e-12f);
        if (lane < 8)
            *(float4*)&outp[(size_t)n * NOUT + cc] =
                make_float4(v[0] / r, v[1] / r, v[2] / r, v[3] / r);
    }
}

// ------------------------- launch -------------------------
extern "C" void kernel_launch(void* const* d_in, const int* in_sizes, int n_in,
                              void* d_out, int out_size) {
    const float* x = (const float*)d_in[0];
    const int* ei = (const int*)d_in[1];
    const int* src = ei;
    const int* dst = ei + NE;
    const float* W0 = (const float*)d_in[2];
    const float* aS0 = (const float*)d_in[3];
    const float* aD0 = (const float*)d_in[4];
    const float* b0 = (const float*)d_in[5];
    const float* Ws0 = (const float*)d_in[6];
    const float* bs0 = (const float*)d_in[7];
    const float* W1 = (const float*)d_in[8];
    const float* aS1 = (const float*)d_in[9];
    const float* aD1 = (const float*)d_in[10];
    const float* b1 = (const float*)d_in[11];
    const float* Ws1 = (const float*)d_in[12];
    const float* bs1 = (const float*)d_in[13];
    const float* W2 = (const float*)d_in[14];
    const float* aS2 = (const float*)d_in[15];
    const float* aD2 = (const float*)d_in[16];
    const float* b2 = (const float*)d_in[17];
    const float* Ws2 = (const float*)d_in[18];
    const float* bs2 = (const float*)d_in[19];
    float* out = (float*)d_out;

    const int SMEM_GEMM = (2 * 128 * SA + 2 * 64 * SA) * 2;  // 104448
    cudaFuncSetAttribute(bgemm64_kernel, cudaFuncAttributeMaxDynamicSharedMemorySize, SMEM_GEMM);

    // ---- CSR build ----
    zero_kernel<<<(NN + 255) / 256, 256>>>();
    count_kernel<<<(NE + 255) / 256, 256>>>(dst);
    scan_kernel<<<1, 1024>>>();
    scatter_kernel<<<(NE + 255) / 256, 256>>>(src, dst);

    int aggBlocks = (NN + 7) / 8;

    // ---- layer 0 ----
    convA_kernel<<<(NTILES * 128 * 32 + 255) / 256, 256>>>(x);
    convB_kernel<<<(256 * 128 + 255) / 256, 256>>>(W0, Ws0, 128, 256, 256);
    bgemm64_kernel<<<dim3(4, NTILES), 256, SMEM_GEMM>>>(bs0, aS0, aD0, 0, NN);
    agg_kernel<<<aggBlocks, 256>>>(SEL_HSKIP, b0, nullptr, 0);

    // ---- layer 1 ----
    convB_kernel<<<(256 * 128 + 255) / 256, 256>>>(W1, Ws1, 128, 256, 256);
    bgemm64_kernel<<<dim3(4, NTILES), 256, SMEM_GEMM>>>(bs1, aS1, aD1, 0, NN);
    agg_kernel<<<aggBlocks, 256>>>(SEL_HSKIP, b1, nullptr, 0);

    // ---- layer 2 ----
    convB_kernel<<<(192 * 128 + 255) / 256, 256>>>(W2, Ws2, 32, 160, 192);
    bgemm64_kernel<<<dim3(3, NTILES), 256, SMEM_GEMM>>>(bs2, aS2, aD2, 1, NN);
    agg_kernel<<<aggBlocks, 256>>>(SEL_HSKIP32, b2, out, 1);
}

// round 12
// speedup vs baseline: 2.3221x; 1.1079x over previous
#include <cuda_runtime.h>
#include <cuda_bf16.h>
#include <cstdint>

#define NN 50000
#define NE 800000
#define HC 128      // HEADS*HID = 4*32
#define NH 4
#define NOUT 32
#define NTILES 391  // ceil(NN/128)
#define SA 136      // padded bf16 row stride

// ------------------------- device scratch -------------------------
__device__ float g_hproj[(size_t)NN * HC];
__device__ float g_hskip[(size_t)NN * HC];
__device__ float g_hskip32[(size_t)NN * NOUT];
__device__ float g_als[(size_t)NN * NH];
__device__ float g_ald[(size_t)NN * NH];
__device__ int   g_deg[NN];
__device__ int   g_cursor[NN];
__device__ int   g_rowptr[NN + 1];
__device__ int   g_csr[NE];
__device__ __nv_bfloat16 g_Ahi[(size_t)NTILES * 128 * SA];
__device__ __nv_bfloat16 g_Alo[(size_t)NTILES * 128 * SA];
__device__ __nv_bfloat16 g_Bhi[3 * 256 * SA];
__device__ __nv_bfloat16 g_Blo[3 * 256 * SA];

#define SEL_HSKIP   2
#define SEL_HSKIP32 5
__device__ __forceinline__ const float* selbuf(int sel) {
    return (sel == SEL_HSKIP) ? g_hskip : g_hskip32;
}

// ------------------------- CSR build -------------------------
__global__ void zero_kernel() {
    int i = blockIdx.x * blockDim.x + threadIdx.x;
    if (i < NN) g_deg[i] = 0;
}
__global__ void count_kernel(const int* __restrict__ dst) {
    int i = blockIdx.x * blockDim.x + threadIdx.x;
    if (i < NE) atomicAdd(&g_deg[dst[i]], 1);
}
// single-block warp-shuffle scan; also seeds g_cursor with rowptr
__global__ void scan_kernel() {
    __shared__ int wsums[32];
    __shared__ int carry;
    int tid = threadIdx.x, lane = tid & 31, wid = tid >> 5;
    if (tid == 0) carry = 0;
    __syncthreads();
    for (int base = 0; base < NN; base += 1024) {
        int i = base + tid;
        int v = (i < NN) ? g_deg[i] : 0;
        int x = v;
#pragma unroll
        for (int o = 1; o < 32; o <<= 1) {
            int y = __shfl_up_sync(0xffffffffu, x, o);
            if (lane >= o) x += y;
        }
        if (lane == 31) wsums[wid] = x;
        __syncthreads();
        if (wid == 0) {
            int s = wsums[lane];
#pragma unroll
            for (int o = 1; o < 32; o <<= 1) {
                int y = __shfl_up_sync(0xffffffffu, s, o);
                if (lane >= o) s += y;
            }
            wsums[lane] = s;
        }
        __syncthreads();
        int wpre = (wid == 0) ? 0 : wsums[wid - 1];
        if (i < NN) {
            int rp = x + wpre + carry - v;
            g_rowptr[i] = rp;
            g_cursor[i] = rp;
        }
        __syncthreads();
        if (tid == 0) carry += wsums[31];
        __syncthreads();
    }
    if (threadIdx.x == 0) g_rowptr[NN] = carry;
}
__global__ void scatter_kernel(const int* __restrict__ src, const int* __restrict__ dst) {
    int i = blockIdx.x * blockDim.x + threadIdx.x;
    if (i < NE) {
        int pos = atomicAdd(&g_cursor[dst[i]], 1);
        g_csr[pos] = src[i];
    }
}

// ------------------------- operand image conversion -------------------------
__device__ __forceinline__ uint32_t pack_bf2(__nv_bfloat16 a, __nv_bfloat16 b) {
    return ((uint32_t)__bfloat16_as_ushort(b) << 16) | __bfloat16_as_ushort(a);
}
__global__ void convA_kernel(const float* __restrict__ src) {
    int idx = blockIdx.x * blockDim.x + threadIdx.x;
    if (idx >= NTILES * 128 * 32) return;
    int n = idx >> 5, c4 = (idx & 31) * 4;
    float4 v = (n < NN) ? *(const float4*)&src[(size_t)n * 128 + c4]
                        : make_float4(0.f, 0.f, 0.f, 0.f);
    float vv[4] = {v.x, v.y, v.z, v.w};
    __nv_bfloat16 hi[4], lo[4];
#pragma unroll
    for (int e = 0; e < 4; e++) {
        hi[e] = __float2bfloat16(vv[e]);
        lo[e] = __float2bfloat16(vv[e] - __bfloat162float(hi[e]));
    }
    size_t a = (size_t)n * SA + c4;
    *(uint2*)&g_Ahi[a] = make_uint2(pack_bf2(hi[0], hi[1]), pack_bf2(hi[2], hi[3]));
    *(uint2*)&g_Alo[a] = make_uint2(pack_bf2(lo[0], lo[1]), pack_bf2(lo[2], lo[3]));
}
// B image rows = output col n ([n][k]); n<128 -> W[k,n]; [128,nv) -> Ws[k,n-128]; [nv,nst) -> 0
__global__ void convB_kernel(const float* __restrict__ W, const float* __restrict__ Ws,
                             int ns, int n_valid, int n_stage, int layer) {
    int idx = blockIdx.x * blockDim.x + threadIdx.x;
    if (idx >= n_stage * 128) return;
    int n = idx >> 7, k = idx & 127;
    float v = 0.f;
    if (n < 128) v = W[(size_t)k * 128 + n];
    else if (n < n_valid) v = Ws[(size_t)k * ns + (n - 128)];
    size_t a = (size_t)layer * 256 * SA + (size_t)n * SA + k;
    __nv_bfloat16 hi = __float2bfloat16(v);
    g_Bhi[a] = hi;
    g_Blo[a] = __float2bfloat16(v - __bfloat162float(hi));
}

// ------------------------- bf16 split HMMA GEMM (ldmatrix, 64-col panels) -------------------------
__device__ __forceinline__ void mma16816(float* c, const uint32_t* a, const uint32_t* b) {
    asm volatile(
        "mma.sync.aligned.m16n8k16.row.col.f32.bf16.bf16.f32 "
        "{%0,%1,%2,%3}, {%4,%5,%6,%7}, {%8,%9}, {%0,%1,%2,%3};"
        : "+f"(c[0]), "+f"(c[1]), "+f"(c[2]), "+f"(c[3])
        : "r"(a[0]), "r"(a[1]), "r"(a[2]), "r"(a[3]), "r"(b[0]), "r"(b[1]));
}
__device__ __forceinline__ void ldsm4(uint32_t* r, const __nv_bfloat16* p) {
    uint32_t addr = (uint32_t)__cvta_generic_to_shared(p);
    asm volatile("ldmatrix.sync.aligned.m8n8.x4.shared.b16 {%0,%1,%2,%3}, [%4];"
                 : "=r"(r[0]), "=r"(r[1]), "=r"(r[2]), "=r"(r[3]) : "r"(addr));
}

// blockIdx.x = panel p. l2mode 0: p0,p1 proj / p2,p3 skip(128-wide). l2mode 1: p0,p1 proj / p2 skip32.
__global__ void __launch_bounds__(256, 2) bgemm64_kernel(
    const float* __restrict__ bias_skip,
    const float* __restrict__ aS, const float* __restrict__ aD,
    int l2mode, int layer, int M) {
    int p = blockIdx.x;
    int bOff, colOff, N, ncols;
    float* C;
    const float* bias;
    bool doAL;
    if (p < 2) {  // proj panels
        bOff = p * 64 * SA; C = g_hproj; colOff = p * 64; N = 128; ncols = 64;
        bias = nullptr; doAL = true;
    } else if (!l2mode) {  // skip panels, layers 0/1
        bOff = p * 64 * SA; C = g_hskip; colOff = (p - 2) * 64; N = 128; ncols = 64;
        bias = bias_skip + colOff; doAL = false;
    } else {  // skip panel, layer 2
        bOff = 128 * SA; C = g_hskip32; colOff = 0; N = 32; ncols = 32;
        bias = bias_skip; doAL = false;
    }
    bOff += layer * 256 * SA;

    extern __shared__ __nv_bfloat16 sm[];
    __nv_bfloat16* sAhi = sm;
    __nv_bfloat16* sAlo = sm + 128 * SA;
    __nv_bfloat16* sBhi = sm + 2 * 128 * SA;
    __nv_bfloat16* sBlo = sBhi + 64 * SA;

    int tid = threadIdx.x;
    int lane = tid & 31, w = tid >> 5;
    int m0 = blockIdx.y * 128;

    // stage: pure uint4 copies
    {
        const uint4* gAh = (const uint4*)(g_Ahi + (size_t)blockIdx.y * 128 * SA);
        const uint4* gAl = (const uint4*)(g_Alo + (size_t)blockIdx.y * 128 * SA);
        uint4* dAh = (uint4*)sAhi;
        uint4* dAl = (uint4*)sAlo;
#pragma unroll
        for (int i = tid; i < 128 * SA / 8; i += 256) { dAh[i] = gAh[i]; dAl[i] = gAl[i]; }
        const uint4* gBh = (const uint4*)(g_Bhi + bOff);
        const uint4* gBl = (const uint4*)(g_Blo + bOff);
        uint4* dBh = (uint4*)sBhi;
        uint4* dBl = (uint4*)sBlo;
#pragma unroll
        for (int i = tid; i < 64 * SA / 8; i += 256) { dBh[i] = gBh[i]; dBl[i] = gBl[i]; }
    }
    __syncthreads();

    int wm = w >> 1, wn = w & 1;
    int mo = wm * 32, no = wn * 32;
    int g = lane >> 2, t = lane & 3;

    // ldmatrix per-lane row/col constants
    int lm = lane >> 3, l7 = lane & 7;
    int rowA = (lm & 1) * 8 + l7, colA = (lm >> 1) * 8;   // A: matrices {r,r+8}x{k,k+8}
    int rowB = (lm >> 1) * 8 + l7, colB = (lm & 1) * 8;   // B: {b[2j][0],b[2j][1],b[2j+1][0],b[2j+1][1]}

    const __nv_bfloat16* pAhi = sAhi + (mo + rowA) * SA + colA;
    const __nv_bfloat16* pAlo = sAlo + (mo + rowA) * SA + colA;
    const __nv_bfloat16* pBhi = sBhi + (no + rowB) * SA + colB;
    const __nv_bfloat16* pBlo = sBlo + (no + rowB) * SA + colB;

    float acc[2][4][4] = {};

#pragma unroll
    for (int k0 = 0; k0 < 128; k0 += 16) {
        uint32_t ah[2][4], al_[2][4], bh[4][2], bl[4][2];
#pragma unroll
        for (int mt = 0; mt < 2; mt++) {
            ldsm4(ah[mt], pAhi + mt * 16 * SA + k0);
            ldsm4(al_[mt], pAlo + mt * 16 * SA + k0);
        }
#pragma unroll
        for (int j = 0; j < 2; j++) {
            ldsm4(&bh[2 * j][0], pBhi + j * 16 * SA + k0);
            ldsm4(&bl[2 * j][0], pBlo + j * 16 * SA + k0);
        }
#pragma unroll
        for (int mt = 0; mt < 2; mt++)
#pragma unroll
            for (int nt = 0; nt < 4; nt++) {
                mma16816(acc[mt][nt], ah[mt], bh[nt]);
                mma16816(acc[mt][nt], al_[mt], bh[nt]);
                mma16816(acc[mt][nt], ah[mt], bl[nt]);
            }
    }

    // epilogue: store C (+bias)
#pragma unroll
    for (int mt = 0; mt < 2; mt++) {
        int row = m0 + mo + mt * 16 + g;
#pragma unroll
        for (int nt = 0; nt < 4; nt++) {
            int cl = no + nt * 8 + 2 * t;
            if (cl >= ncols) continue;
            float b0 = 0.f, b1 = 0.f;
            if (bias) { b0 = __ldg(&bias[cl]); b1 = __ldg(&bias[cl + 1]); }
            if (row < M)
                *(float2*)&C[(size_t)row * N + colOff + cl] =
                    make_float2(acc[mt][nt][0] + b0, acc[mt][nt][1] + b1);
            if (row + 8 < M)
                *(float2*)&C[(size_t)(row + 8) * N + colOff + cl] =
                    make_float2(acc[mt][nt][2] + b0, acc[mt][nt][3] + b1);
        }
    }

    // fused attention logits: warp's 32 cols = head (colOff+no)/32
    if (doAL) {
        int head = (colOff + no) >> 5;
        float sS[2][2], sD[2][2];
#pragma unroll
        for (int mt = 0; mt < 2; mt++) { sS[mt][0] = sS[mt][1] = sD[mt][0] = sD[mt][1] = 0.f; }
#pragma unroll
        for (int nt = 0; nt < 4; nt++) {
            int col = colOff + no + nt * 8 + 2 * t;
            float c0s = __ldg(&aS[col]), c1s = __ldg(&aS[col + 1]);
            float c0d = __ldg(&aD[col]), c1d = __ldg(&aD[col + 1]);
#pragma unroll
            for (int mt = 0; mt < 2; mt++) {
                sS[mt][0] += acc[mt][nt][0] * c0s + acc[mt][nt][1] * c1s;
                sS[mt][1] += acc[mt][nt][2] * c0s + acc[mt][nt][3] * c1s;
                sD[mt][0] += acc[mt][nt][0] * c0d + acc[mt][nt][1] * c1d;
                sD[mt][1] += acc[mt][nt][2] * c0d + acc[mt][nt][3] * c1d;
            }
        }
#pragma unroll
        for (int mt = 0; mt < 2; mt++)
#pragma unroll
            for (int half = 0; half < 2; half++) {
                sS[mt][half] += __shfl_xor_sync(0xffffffffu, sS[mt][half], 1);
                sS[mt][half] += __shfl_xor_sync(0xffffffffu, sS[mt][half], 2);
                sD[mt][half] += __shfl_xor_sync(0xffffffffu, sD[mt][half], 1);
                sD[mt][half] += __shfl_xor_sync(0xffffffffu, sD[mt][half], 2);
            }
        if (t == 0) {
#pragma unroll
            for (int mt = 0; mt < 2; mt++) {
                int row = m0 + mo + mt * 16 + g;
                if (row < M) { g_als[(size_t)row * 4 + head] = sS[mt][0]; g_ald[(size_t)row * 4 + head] = sD[mt][0]; }
                if (row + 8 < M) { g_als[(size_t)(row + 8) * 4 + head] = sS[mt][1]; g_ald[(size_t)(row + 8) * 4 + head] = sD[mt][1]; }
            }
        }
    }
}

__device__ __forceinline__ float lrelu(float x) { return x > 0.f ? x : 0.2f * x; }

// ------------------------- aggregation (2 passes, no-max softmax, float4 gather) -------------------------
__global__ void agg_kernel(int skipsel, const float* __restrict__ bias,
                           float* __restrict__ outp, int mode) {
    const float* hskip = selbuf(skipsel);
    const int WPB = 8;
    __shared__ float sh_alpha[WPB][32][4];
    __shared__ int sh_src[WPB][32];
    int w = threadIdx.x >> 5;
    int lane = threadIdx.x & 31;
    int n = blockIdx.x * WPB + w;
    if (n >= NN) return;
    int beg = g_rowptr[n], end = g_rowptr[n + 1];
    float4 ad = *(const float4*)&g_ald[(size_t)n * 4];

    float s0 = 0.f, s1 = 0.f, s2 = 0.f, s3 = 0.f;
    for (int j = beg + lane; j < end; j += 32) {
        int s = __ldg(&g_csr[j]);
        float4 a = __ldg((const float4*)&g_als[(size_t)s * 4]);
        s0 += __expf(lrelu(a.x + ad.x));
        s1 += __expf(lrelu(a.y + ad.y));
        s2 += __expf(lrelu(a.z + ad.z));
        s3 += __expf(lrelu(a.w + ad.w));
    }
#pragma unroll
    for (int o = 16; o > 0; o >>= 1) {
        s0 += __shfl_xor_sync(0xffffffffu, s0, o);
        s1 += __shfl_xor_sync(0xffffffffu, s1, o);
        s2 += __shfl_xor_sync(0xffffffffu, s2, o);
        s3 += __shfl_xor_sync(0xffffffffu, s3, o);
    }
    float inv0 = 1.f / (s0 + 1e-16f);
    float inv1 = 1.f / (s1 + 1e-16f);
    float inv2 = 1.f / (s2 + 1e-16f);
    float inv3 = 1.f / (s3 + 1e-16f);

    int hsel = lane >> 3;
    float4 acc = make_float4(0.f, 0.f, 0.f, 0.f);
    for (int base = beg; base < end; base += 32) {
        int j = base + lane;
        if (j < end) {
            int sr = g_csr[j];
            sh_src[w][lane] = sr;
            float4 a = __ldg((const float4*)&g_als[(size_t)sr * 4]);
            sh_alpha[w][lane][0] = __expf(lrelu(a.x + ad.x)) * inv0;
            sh_alpha[w][lane][1] = __expf(lrelu(a.y + ad.y)) * inv1;
            sh_alpha[w][lane][2] = __expf(lrelu(a.z + ad.z)) * inv2;
            sh_alpha[w][lane][3] = __expf(lrelu(a.w + ad.w)) * inv3;
        }
        __syncwarp();
        int cnt = min(32, end - base);
#pragma unroll 4
        for (int k = 0; k < cnt; k++) {
            int sr = sh_src[w][k];
            float av = sh_alpha[w][k][hsel];
            float4 hv = *(const float4*)&g_hproj[(size_t)sr * HC + 4 * lane];
            acc.x += av * hv.x;
            acc.y += av * hv.y;
            acc.z += av * hv.z;
            acc.w += av * hv.w;
        }
        __syncwarp();
    }

    if (mode == 0) {
        float4 bb = __ldg((const float4*)&bias[4 * lane]);
        float4 sk = *(const float4*)&hskip[(size_t)n * HC + 4 * lane];
        float v[4] = {acc.x + bb.x + sk.x, acc.y + bb.y + sk.y,
                      acc.z + bb.z + sk.z, acc.w + bb.w + sk.w};
        __nv_bfloat16 hi[4], lo[4];
#pragma unroll
        for (int e = 0; e < 4; e++) {
            v[e] = v[e] > 0.f ? v[e] : expm1f(v[e]);
            hi[e] = __float2bfloat16(v[e]);
            lo[e] = __float2bfloat16(v[e] - __bfloat162float(hi[e]));
        }
        size_t a = (size_t)n * SA + 4 * lane;
        *(uint2*)&g_Ahi[a] = make_uint2(pack_bf2(hi[0], hi[1]), pack_bf2(hi[2], hi[3]));
        *(uint2*)&g_Alo[a] = make_uint2(pack_bf2(lo[0], lo[1]), pack_bf2(lo[2], lo[3]));
    } else {
#pragma unroll
        for (int o = 8; o <= 16; o <<= 1) {
            acc.x += __shfl_xor_sync(0xffffffffu, acc.x, o);
            acc.y += __shfl_xor_sync(0xffffffffu, acc.y, o);
            acc.z += __shfl_xor_sync(0xffffffffu, acc.z, o);
            acc.w += __shfl_xor_sync(0xffffffffu, acc.w, o);
        }
        int cc = 4 * (lane & 7);
        float4 bb = __ldg((const float4*)&bias[cc]);
        float4 sk = *(const float4*)&hskip[(size_t)n * NOUT + cc];
        float v[4] = {0.25f * acc.x + bb.x + sk.x, 0.25f * acc.y + bb.y + sk.y,
                      0.25f * acc.z + bb.z + sk.z, 0.25f * acc.w + bb.w + sk.w};
        float ss = v[0] * v[0] + v[1] * v[1] + v[2] * v[2] + v[3] * v[3];
#pragma unroll
        for (int o = 1; o <= 4; o <<= 1) ss += __shfl_xor_sync(0xffffffffu, ss, o);
        float r = fmaxf(sqrtf(ss), 1e-12f);
        if (lane < 8)
            *(float4*)&outp[(size_t)n * NOUT + cc] =
                make_float4(v[0] / r, v[1] / r, v[2] / r, v[3] / r);
    }
}

// ------------------------- launch -------------------------
extern "C" void kernel_launch(void* const* d_in, const int* in_sizes, int n_in,
                              void* d_out, int out_size) {
    const float* x = (const float*)d_in[0];
    const int* ei = (const int*)d_in[1];
    const int* src = ei;
    const int* dst = ei + NE;
    const float* W0 = (const float*)d_in[2];
    const float* aS0 = (const float*)d_in[3];
    const float* aD0 = (const float*)d_in[4];
    const float* b0 = (const float*)d_in[5];
    const float* Ws0 = (const float*)d_in[6];
    const float* bs0 = (const float*)d_in[7];
    const float* W1 = (const float*)d_in[8];
    const float* aS1 = (const float*)d_in[9];
    const float* aD1 = (const float*)d_in[10];
    const float* b1 = (const float*)d_in[11];
    const float* Ws1 = (const float*)d_in[12];
    const float* bs1 = (const float*)d_in[13];
    const float* W2 = (const float*)d_in[14];
    const float* aS2 = (const float*)d_in[15];
    const float* aD2 = (const float*)d_in[16];
    const float* b2 = (const float*)d_in[17];
    const float* Ws2 = (const float*)d_in[18];
    const float* bs2 = (const float*)d_in[19];
    float* out = (float*)d_out;

    const int SMEM_GEMM = (2 * 128 * SA + 2 * 64 * SA) * 2;  // 104448

    // one-time setup (first call is the non-capturing correctness run)
    static cudaStream_t side = nullptr;
    static cudaEvent_t evFork = nullptr, evJoin = nullptr;
    static bool inited = false;
    if (!inited) {
        cudaFuncSetAttribute(bgemm64_kernel, cudaFuncAttributeMaxDynamicSharedMemorySize, SMEM_GEMM);
        cudaStreamCreateWithFlags(&side, cudaStreamNonBlocking);
        cudaEventCreateWithFlags(&evFork, cudaEventDisableTiming);
        cudaEventCreateWithFlags(&evJoin, cudaEventDisableTiming);
        inited = true;
    }

    int aggBlocks = (NN + 7) / 8;

    // ---- fork: CSR build on side stream, overlapped with conv + layer-0 GEMM ----
    cudaEventRecord(evFork, 0);
    cudaStreamWaitEvent(side, evFork, 0);
    zero_kernel<<<(NN + 255) / 256, 256, 0, side>>>();
    count_kernel<<<(NE + 255) / 256, 256, 0, side>>>(dst);
    scan_kernel<<<1, 1024, 0, side>>>();
    scatter_kernel<<<(NE + 255) / 256, 256, 0, side>>>(src, dst);
    cudaEventRecord(evJoin, side);

    // main stream: conversions + layer-0 GEMM (independent of CSR)
    convA_kernel<<<(NTILES * 128 * 32 + 255) / 256, 256>>>(x);
    convB_kernel<<<(256 * 128 + 255) / 256, 256>>>(W0, Ws0, 128, 256, 256, 0);
    convB_kernel<<<(256 * 128 + 255) / 256, 256>>>(W1, Ws1, 128, 256, 256, 1);
    convB_kernel<<<(192 * 128 + 255) / 256, 256>>>(W2, Ws2, 32, 160, 192, 2);
    bgemm64_kernel<<<dim3(4, NTILES), 256, SMEM_GEMM>>>(bs0, aS0, aD0, 0, 0, NN);

    // join: agg needs CSR
    cudaStreamWaitEvent(0, evJoin, 0);
    agg_kernel<<<aggBlocks, 256>>>(SEL_HSKIP, b0, nullptr, 0);

    // ---- layer 1 ----
    bgemm64_kernel<<<dim3(4, NTILES), 256, SMEM_GEMM>>>(bs1, aS1, aD1, 0, 1, NN);
    agg_kernel<<<aggBlocks, 256>>>(SEL_HSKIP, b1, nullptr, 0);

    // ---- layer 2 ----
    bgemm64_kernel<<<dim3(3, NTILES), 256, SMEM_GEMM>>>(bs2, aS2, aD2, 1, 2, NN);
    agg_kernel<<<aggBlocks, 256>>>(SEL_HSKIP32, b2, out, 1);
}